// round 4
// baseline (speedup 1.0000x reference)
#include <cuda_runtime.h>

#define Nn 2048
#define Ee 65536
#define GRID 148
#define TPB 256

// ---------------- scratch (device globals; no allocations) ----------------
__device__ __align__(16) float g_feat[Nn*320];     // [x | h1 | h2]
__device__ __align__(16) float g_xWr[Nn*136];      // cols 0..127 = xW, col 128 = xr
__device__ __align__(16) float g_S[Nn*128];
__device__ __align__(16) float g_ealpha[Ee];
__device__ __align__(16) float g_den[Nn];          // invariant: zero at phase entry
__device__ __align__(16) float g_ab[Nn*40];
__device__ __align__(16) float g_W1p[40*320];
__device__ __align__(16) float g_B0p[129*64];
__device__ __align__(16) float g_B1p[129*128];
__device__ __align__(16) float g_w1e[256];
__device__ int g_deg[Nn];                          // invariant: zero (restored by scan)
__device__ int g_off[Nn+1];
__device__ int g_cur[Nn];
__device__ int g_perm[Ee];
__device__ unsigned g_barCount;
__device__ unsigned g_barGen;

__device__ __forceinline__ float lrelu(float x) { return x > 0.f ? x : 0.01f*x; }

// ---------------- grid-wide barrier (all 148 blocks resident: single wave) ----
__device__ __forceinline__ void gsync() {
  __syncthreads();
  if (threadIdx.x == 0) {
    unsigned gen;
    asm volatile("ld.acquire.gpu.global.u32 %0, [%1];" : "=r"(gen) : "l"(&g_barGen));
    __threadfence();
    unsigned t = atomicAdd(&g_barCount, 1u);
    if (t == GRID - 1) {
      atomicExch(&g_barCount, 0u);
      __threadfence();
      atomicAdd(&g_barGen, 1u);
    } else {
      unsigned cur;
      do {
        asm volatile("ld.acquire.gpu.global.u32 %0, [%1];" : "=r"(cur) : "l"(&g_barGen));
      } while (cur == gen);
    }
  }
  __syncthreads();
}

// ---------------- shared-memory overlays ----------------
struct GemmSm  { float As[32][65]; float Bs[32][65]; };                     // 16640 B
struct FinalSm { float ash[8][20]; float w2s[20]; float rowM[8]; float rowInv[8];
                 float2 red[256]; float btile[256][21]; };                  // 24336 B
struct AggrSm  { float4 red4[256]; float sinv; };                           //  4100 B
struct ScanSm  { int sw[8]; };

// ---------------- device GEMM: C = act(A[2048,K] @ B[Nc,K]^T + bias) ----------
__device__ void dgemm(const float* __restrict__ A, int lda,
                      const float* __restrict__ B, int ldb,
                      const float* __restrict__ bias,
                      float* __restrict__ C, int ldc,
                      int Ncols, int K, int ntiles, bool act, char* sm) {
  GemmSm* s = (GemmSm*)sm;
  int tid = threadIdx.x;
  int tx = tid & 15, ty = tid >> 4;
  for (int t = blockIdx.x; t < ntiles; t += GRID) {
    int m0 = (t & 31) * 64, n0 = (t >> 5) * 64;
    float acc[4][4] = {};
    for (int k0 = 0; k0 < K; k0 += 32) {
      #pragma unroll
      for (int i = 0; i < 8; i++) {
        int l = tid + i*256;
        int r = l >> 5, c = l & 31;
        s->As[c][r] = A[(m0+r)*lda + (k0+c)];
        int rn = n0 + r;
        s->Bs[c][r] = (rn < Ncols) ? B[rn*ldb + (k0+c)] : 0.f;
      }
      __syncthreads();
      #pragma unroll
      for (int k = 0; k < 32; k++) {
        float av[4], bv[4];
        #pragma unroll
        for (int i = 0; i < 4; i++) av[i] = s->As[k][ty*4+i];
        #pragma unroll
        for (int j = 0; j < 4; j++) bv[j] = s->Bs[k][tx*4+j];
        #pragma unroll
        for (int i = 0; i < 4; i++)
          #pragma unroll
          for (int j = 0; j < 4; j++)
            acc[i][j] += av[i]*bv[j];
      }
      __syncthreads();
    }
    #pragma unroll
    for (int i = 0; i < 4; i++) {
      int mm = m0 + ty*4 + i;
      #pragma unroll
      for (int j = 0; j < 4; j++) {
        int nn = n0 + tx*4 + j;
        if (nn < Ncols) {
          float v = acc[i][j];
          if (bias) v += bias[nn];
          if (act) v = fmaxf(v, 0.f);
          C[mm*ldc + nn] = v;
        }
      }
    }
  }
}

// ---------------- edge: alpha numerators + denominator atomics ----------------
__device__ void edge_ev(const int* __restrict__ esrc, const int* __restrict__ edst,
                        const float* __restrict__ eattr, int w1off,
                        const float* __restrict__ attl) {
  int lane = threadIdx.x & 31;
  int gw = blockIdx.x*(TPB/32) + (threadIdx.x >> 5);
  const float4* xw4 = (const float4*)g_xWr;
  float4 wv = ((const float4*)(g_w1e + w1off))[lane];
  float4 av = ((const float4*)attl)[lane];
  for (int e = gw; e < Ee; e += GRID*(TPB/32)) {
    int src = esrc[e];
    float ea = eattr[e];
    float4 xv = xw4[src*34 + lane];
    float p = lrelu(xv.x + ea*wv.x)*av.x + lrelu(xv.y + ea*wv.y)*av.y
            + lrelu(xv.z + ea*wv.z)*av.z + lrelu(xv.w + ea*wv.w)*av.w;
    #pragma unroll
    for (int s = 16; s > 0; s >>= 1) p += __shfl_xor_sync(0xffffffffu, p, s);
    if (lane == 0) {
      int dst = edst[e];
      float ev = __expf(lrelu(p + g_xWr[dst*136 + 128]));
      g_ealpha[e] = ev;
      atomicAdd(&g_den[dst], ev);
    }
  }
}

// ---------------- edge: per-dst weighted aggregation (restores den=0) ---------
__device__ void edge_aggr(const int* __restrict__ esrc, const float* __restrict__ eattr,
                          int w1off, char* sm) {
  AggrSm* a = (AggrSm*)sm;
  int tid = threadIdx.x, w = tid >> 5, g = tid & 31;
  const float4* xw4 = (const float4*)g_xWr;
  float4 wv = ((const float4*)(g_w1e + w1off))[g];
  for (int n = blockIdx.x; n < Nn; n += GRID) {
    int begin = g_off[n], cnt = g_off[n+1] - begin;
    if (tid == 0) { a->sinv = 1.f/(g_den[n] + 1e-16f); g_den[n] = 0.f; }
    __syncthreads();
    float inv = a->sinv;
    float ax=0.f, ay=0.f, az=0.f, aw=0.f;
    for (int j0 = 0; j0 < cnt; j0 += 8) {
      int j = j0 + w;
      if (j < cnt) {
        int e = g_perm[begin+j];
        float wt = g_ealpha[e]*inv;
        float ea = eattr[e];
        float4 xv = xw4[esrc[e]*34 + g];
        ax += wt*lrelu(xv.x + ea*wv.x);
        ay += wt*lrelu(xv.y + ea*wv.y);
        az += wt*lrelu(xv.z + ea*wv.z);
        aw += wt*lrelu(xv.w + ea*wv.w);
      }
    }
    a->red4[tid] = make_float4(ax, ay, az, aw);
    __syncthreads();
    if (w == 0) {
      float4 r = a->red4[g];
      #pragma unroll
      for (int s = 1; s < 8; s++) {
        float4 o = a->red4[s*32 + g];
        r.x += o.x; r.y += o.y; r.z += o.z; r.w += o.w;
      }
      ((float4*)g_S)[n*32 + g] = r;
    }
    __syncthreads();
  }
}

// ---------------- pairwise MLP + masked row softmax for one 8-row group -------
__device__ void final_group(int i0, const float* __restrict__ b1,
                            const float* __restrict__ W2, const float* __restrict__ b2,
                            const float* __restrict__ m, float* __restrict__ out,
                            char* sm) {
  FinalSm* f = (FinalSm*)sm;
  int tid = threadIdx.x;
  if (tid < 160) {
    int r = tid / 20, c = tid - r*20;
    f->ash[r][c] = g_ab[(i0+r)*40 + c] + b1[c];
  }
  if (tid < 20) f->w2s[tid] = W2[tid];
  float b2v = b2[0];
  float omax[8], osum[8];
  #pragma unroll
  for (int r = 0; r < 8; r++) { omax[r] = -1e30f; osum[r] = 0.f; }
  for (int jt = 0; jt < Nn; jt += 256) {
    __syncthreads();
    #pragma unroll
    for (int u = 0; u < 20; u++) {
      int l = u*256 + tid;
      int t = l / 20, c = l - t*20;
      f->btile[t][c] = g_ab[(jt+t)*40 + 20 + c];
    }
    __syncthreads();
    int j = jt + tid;
    float bl[20];
    #pragma unroll
    for (int c = 0; c < 20; c++) bl[c] = f->btile[tid][c];
    #pragma unroll
    for (int r = 0; r < 8; r++) {
      float acc = 0.f;
      #pragma unroll
      for (int c = 0; c < 20; c++) acc += fmaxf(f->ash[r][c] + bl[c], 0.f) * f->w2s[c];
      size_t idx = (size_t)(i0+r)*Nn + j;
      float lv = (acc + b2v) * m[idx];
      out[idx] = lv;                       // park raw logit
      float nm = fmaxf(omax[r], lv);
      osum[r] = osum[r]*__expf(omax[r]-nm) + __expf(lv-nm);
      omax[r] = nm;
    }
  }
  for (int r = 0; r < 8; r++) {
    __syncthreads();
    f->red[tid] = make_float2(omax[r], osum[r]);
    __syncthreads();
    for (int s = 128; s > 0; s >>= 1) {
      if (tid < s) {
        float2 A = f->red[tid], B = f->red[tid+s];
        float M = fmaxf(A.x, B.x);
        f->red[tid] = make_float2(M, A.y*__expf(A.x-M) + B.y*__expf(B.x-M));
      }
      __syncthreads();
    }
    if (tid == 0) { f->rowM[r] = f->red[0].x; f->rowInv[r] = 1.f/f->red[0].y; }
  }
  __syncthreads();
  for (int jt = 0; jt < Nn; jt += 256) {
    int j = jt + tid;
    #pragma unroll
    for (int r = 0; r < 8; r++) {
      size_t idx = (size_t)(i0+r)*Nn + j;
      out[idx] = __expf(out[idx] - f->rowM[r]) * f->rowInv[r];
    }
  }
}

// ---------------- the mega kernel ----------------
__global__ void __launch_bounds__(TPB, 1)
k_mega(const int* __restrict__ node_ids, const int* __restrict__ eidx,
       const float* __restrict__ eattr, const float* __restrict__ m,
       const float* __restrict__ emb,
       const float* __restrict__ l0_lin1, const float* __restrict__ l0_lin2,
       const float* __restrict__ l0_attl, const float* __restrict__ l0_attr,
       const float* __restrict__ l0_bias,
       const float* __restrict__ l1_lin1, const float* __restrict__ l1_lin2,
       const float* __restrict__ l1_attl, const float* __restrict__ l1_attr,
       const float* __restrict__ l1_bias,
       const float* __restrict__ W1, const float* __restrict__ b1,
       const float* __restrict__ W2, const float* __restrict__ b2,
       float* __restrict__ out) {
  __shared__ __align__(16) char SM[24384];
  const int* esrc = eidx;
  const int* edst = eidx + Ee;
  int tid = threadIdx.x;

  // ---- Phase A: setup (embed + packs + degree histogram) ----
  for (int b = blockIdx.x; b < 917; b += GRID) {
    if (b < 512) {
      int node = b*4 + (tid >> 6);
      int col = tid & 63;
      g_feat[node*320 + col] = emb[node_ids[node]*64 + col];
    } else if (b < 562) {
      int i = (b-512)*256 + tid;
      if (i < 40*320) {
        int r = i/320, c = i - r*320;
        g_W1p[i] = (r < 20) ? W1[r*640 + c] : W1[(r-20)*640 + 320 + c];
      }
    } else if (b == 562) {
      if (tid < 128) {
        g_w1e[tid]       = l0_lin1[tid*65  + 64];
        g_w1e[128 + tid] = l1_lin1[tid*129 + 128];
      }
    } else if (b < 596) {
      int i = (b-563)*256 + tid;
      if (i < 129*64) {
        int r = i >> 6, c = i & 63;
        g_B0p[i] = (r < 128) ? l0_lin1[r*65 + c] : l0_attr[c];
      }
    } else if (b < 661) {
      int i = (b-596)*256 + tid;
      if (i < 129*128) {
        int r = i >> 7, c = i & 127;
        g_B1p[i] = (r < 128) ? l1_lin1[r*129 + c] : l1_attr[c];
      }
    } else {
      int e = (b-661)*256 + tid;
      atomicAdd(&g_deg[edst[e]], 1);
    }
  }
  gsync();

  // ---- Phase B: xW0 GEMM (blocks 0..95) || CSR scan (block 96) ----
  dgemm(g_feat, 320, g_B0p, 64, nullptr, g_xWr, 136, 129, 64, 96, false, SM);
  if (blockIdx.x == 96) {
    ScanSm* sc = (ScanSm*)SM;
    int base = tid*8;
    int v[8], run = 0;
    #pragma unroll
    for (int i = 0; i < 8; i++) { v[i] = g_deg[base+i]; run += v[i]; }
    int lane = tid & 31, wid = tid >> 5;
    int incl = run;
    #pragma unroll
    for (int o = 1; o < 32; o <<= 1) {
      int u = __shfl_up_sync(0xffffffffu, incl, o);
      if (lane >= o) incl += u;
    }
    if (lane == 31) sc->sw[wid] = incl;
    __syncthreads();
    if (tid == 0) {
      int acc = 0;
      #pragma unroll
      for (int w = 0; w < 8; w++) { int x = sc->sw[w]; sc->sw[w] = acc; acc += x; }
    }
    __syncthreads();
    int off = sc->sw[wid] + incl - run;
    #pragma unroll
    for (int i = 0; i < 8; i++) {
      g_off[base+i] = off; g_cur[base+i] = off;
      off += v[i];
      g_deg[base+i] = 0;                  // restore invariant
    }
    if (tid == 0) g_off[2048] = Ee;
  }
  gsync();

  // ---- Phase C: scatter + edge alpha layer0 ----
  for (int e = blockIdx.x*TPB + tid; e < Ee; e += GRID*TPB) {
    int p = atomicAdd(&g_cur[edst[e]], 1);
    g_perm[p] = e;
  }
  edge_ev(esrc, edst, eattr, 0, l0_attl);
  gsync();

  // ---- Phase D: aggregation layer0 ----
  edge_aggr(esrc, eattr, 0, SM);
  gsync();

  // ---- Phase E: h1 GEMM ----
  dgemm(g_S, 128, l0_lin2, 128, l0_bias, g_feat + 64, 320, 128, 128, 64, true, SM);
  gsync();

  // ---- Phase F: xW1 GEMM ----
  dgemm(g_feat + 64, 320, g_B1p, 128, nullptr, g_xWr, 136, 129, 128, 96, false, SM);
  gsync();

  // ---- Phase G: edge alpha layer1 ----
  edge_ev(esrc, edst, eattr, 128, l1_attl);
  gsync();

  // ---- Phase H: aggregation layer1 ----
  edge_aggr(esrc, eattr, 128, SM);
  gsync();

  // ---- Phase I: h2 GEMM ----
  dgemm(g_S, 128, l1_lin2, 128, l1_bias, g_feat + 192, 320, 128, 128, 64, true, SM);
  gsync();

  // ---- Phase J: a|b GEMM ----
  dgemm(g_feat, 320, g_W1p, 320, nullptr, g_ab, 40, 40, 320, 32, false, SM);
  gsync();

  // ---- Phase K: pairwise MLP + masked softmax ----
  for (int grp = blockIdx.x; grp < Nn/8; grp += GRID) {
    final_group(grp*8, b1, W2, b2, m, out, SM);
    __syncthreads();
  }
}

// ---------------- driver ----------------
extern "C" void kernel_launch(void* const* d_in, const int* in_sizes, int n_in,
                              void* d_out, int out_size) {
  const int*   node_ids = (const int*)  d_in[0];
  const int*   eidx     = (const int*)  d_in[1];
  const float* eattr    = (const float*)d_in[2];
  const float* m        = (const float*)d_in[3];
  const float* emb      = (const float*)d_in[4];
  const float* l0_lin1  = (const float*)d_in[5];
  const float* l0_lin2  = (const float*)d_in[6];
  const float* l0_attl  = (const float*)d_in[7];
  const float* l0_attr  = (const float*)d_in[8];
  const float* l0_bias  = (const float*)d_in[9];
  const float* l1_lin1  = (const float*)d_in[10];
  const float* l1_lin2  = (const float*)d_in[11];
  const float* l1_attl  = (const float*)d_in[12];
  const float* l1_attr  = (const float*)d_in[13];
  const float* l1_bias  = (const float*)d_in[14];
  const float* W1       = (const float*)d_in[15];
  const float* b1       = (const float*)d_in[16];
  const float* W2       = (const float*)d_in[17];
  const float* b2       = (const float*)d_in[18];
  float* out = (float*)d_out;

  k_mega<<<GRID, TPB>>>(node_ids, eidx, eattr, m, emb,
                        l0_lin1, l0_lin2, l0_attl, l0_attr, l0_bias,
                        l1_lin1, l1_lin2, l1_attl, l1_attr, l1_bias,
                        W1, b1, W2, b2, out);
}

// round 5
// speedup vs baseline: 2.4872x; 2.4872x over previous
#include <cuda_runtime.h>

#define Nn 2048
#define Ee 65536

// ---------------- scratch (device globals; no allocations) ----------------
__device__ __align__(16) float g_feat[Nn*320];     // [x | h1 | h2]
__device__ __align__(16) float g_xWr[Nn*136];      // cols 0..127 = xW, col 128 = xr
__device__ __align__(16) float g_S[Nn*128];
__device__ __align__(16) float g_ealpha[Ee];
__device__ __align__(16) float g_den[Nn];          // invariant: zero at entry (restored by aggr)
__device__ __align__(16) float g_ab[Nn*40];        // zeroed in setup (split-K atomics)
__device__ __align__(16) float g_W1p[40*320];
__device__ __align__(16) float g_B0p[129*64];
__device__ __align__(16) float g_B1p[129*128];
__device__ __align__(16) float g_w1e[256];
__device__ int g_deg[Nn];                          // invariant: zero (restored by scan)
__device__ int g_off[Nn+1];
__device__ int g_cur[Nn];
__device__ int g_perm[Ee];

__device__ __forceinline__ float lrelu(float x) { return x > 0.f ? x : 0.01f*x; }

__device__ __forceinline__ float* sel_ptr(int s) {
  switch (s) {
    case 0: return g_feat;
    case 1: return g_S;
    case 2: return g_xWr;
    case 3: return g_W1p;
    case 4: return g_B0p;
    case 5: return g_B1p;
    case 6: return g_ab;
    default: return nullptr;
  }
}

// ---------------- fused setup: embed + packs + hist + ab-zero ----------------
__global__ void k_setup(const int* __restrict__ ids, const float* __restrict__ emb,
                        const float* __restrict__ W1,
                        const float* __restrict__ l0_lin1, const float* __restrict__ l1_lin1,
                        const float* __restrict__ l0_attr, const float* __restrict__ l1_attr,
                        const int* __restrict__ edst) {
  int b = blockIdx.x, tid = threadIdx.x;
  if (b < 512) {
    int node = b*4 + (tid >> 6);
    int col = tid & 63;
    g_feat[node*320 + col] = emb[ids[node]*64 + col];
  } else if (b < 562) {
    int i = (b-512)*256 + tid;
    if (i < 40*320) {
      int r = i/320, c = i - r*320;
      g_W1p[i] = (r < 20) ? W1[r*640 + c] : W1[(r-20)*640 + 320 + c];
    }
  } else if (b == 562) {
    if (tid < 128) {
      g_w1e[tid]       = l0_lin1[tid*65  + 64];
      g_w1e[128 + tid] = l1_lin1[tid*129 + 128];
    }
  } else if (b < 596) {
    int i = (b-563)*256 + tid;
    if (i < 129*64) {
      int r = i >> 6, c = i & 63;
      g_B0p[i] = (r < 128) ? l0_lin1[r*65 + c] : l0_attr[c];
    }
  } else if (b < 661) {
    int i = (b-596)*256 + tid;
    if (i < 129*128) {
      int r = i >> 7, c = i & 127;
      g_B1p[i] = (r < 128) ? l1_lin1[r*129 + c] : l1_attr[c];
    }
  } else if (b < 917) {
    int e = (b-661)*256 + tid;
    atomicAdd(&g_deg[edst[e]], 1);
  } else {
    g_ab[(b-917)*256 + tid] = 0.f;     // 320 blocks: 81920 floats
  }
}

// ---------------- scan (256 threads), restores g_deg=0 ----------------
__device__ void dev_scan() {
  __shared__ int sw[8];
  int tid = threadIdx.x;
  int base = tid*8;
  int v[8], run = 0;
  #pragma unroll
  for (int i = 0; i < 8; i++) { v[i] = g_deg[base+i]; run += v[i]; }
  int lane = tid & 31, wid = tid >> 5;
  int incl = run;
  #pragma unroll
  for (int o = 1; o < 32; o <<= 1) {
    int u = __shfl_up_sync(0xffffffffu, incl, o);
    if (lane >= o) incl += u;
  }
  if (lane == 31) sw[wid] = incl;
  __syncthreads();
  if (tid == 0) {
    int acc = 0;
    #pragma unroll
    for (int w = 0; w < 8; w++) { int x = sw[w]; sw[w] = acc; acc += x; }
  }
  __syncthreads();
  int off = sw[wid] + incl - run;
  #pragma unroll
  for (int i = 0; i < 8; i++) {
    g_off[base+i] = off; g_cur[base+i] = off;
    off += v[i];
    g_deg[base+i] = 0;
  }
  if (tid == 0) g_off[2048] = Ee;
}

// ---------------- double-buffered 64x64 GEMM: C = act(A @ B^T + bias) --------
template<int ACT, int ATOMIC>
__global__ void __launch_bounds__(256)
k_gemm(int Asel, int aoff, int lda, int Bsel, const float* __restrict__ Bext, int ldb,
       const float* __restrict__ bias, int Csel, int coff, int ldc,
       int Ncols, int K, int nMt, int ntiles, int withScan) {
  if (withScan && (int)blockIdx.x == ntiles) { dev_scan(); return; }
  if ((int)blockIdx.x >= ntiles) return;
  __shared__ __align__(16) float As[2][32][68];
  __shared__ __align__(16) float Bs[2][32][68];
  int koff = blockIdx.y * 64;
  const float* A = sel_ptr(Asel) + aoff + koff;
  const float* B = (Bsel >= 0 ? sel_ptr(Bsel) : Bext) + koff;
  float* C = sel_ptr(Csel) + coff;
  int tid = threadIdx.x;
  int tx = tid & 15, ty = tid >> 4;
  int tile = blockIdx.x;
  int m0 = (tile % nMt)*64, n0 = (tile / nMt)*64;
  int lr = tid >> 3;            // 0..31
  int ca = (tid & 7)*4;
  int rn0 = n0 + lr, rn1 = rn0 + 32;
  float4 ra0, ra1, rb0, rb1;
  const float4 z4 = make_float4(0.f,0.f,0.f,0.f);

  #define LDG_CHUNK(k0)                                                        \
    ra0 = *(const float4*)&A[(m0+lr)*lda + (k0) + ca];                         \
    ra1 = *(const float4*)&A[(m0+lr+32)*lda + (k0) + ca];                      \
    rb0 = (rn0 < Ncols) ? *(const float4*)&B[rn0*ldb + (k0) + ca] : z4;        \
    rb1 = (rn1 < Ncols) ? *(const float4*)&B[rn1*ldb + (k0) + ca] : z4;

  #define STS_CHUNK(buf)                                                       \
    As[buf][ca+0][lr] = ra0.x; As[buf][ca+1][lr] = ra0.y;                      \
    As[buf][ca+2][lr] = ra0.z; As[buf][ca+3][lr] = ra0.w;                      \
    As[buf][ca+0][lr+32] = ra1.x; As[buf][ca+1][lr+32] = ra1.y;                \
    As[buf][ca+2][lr+32] = ra1.z; As[buf][ca+3][lr+32] = ra1.w;                \
    Bs[buf][ca+0][lr] = rb0.x; Bs[buf][ca+1][lr] = rb0.y;                      \
    Bs[buf][ca+2][lr] = rb0.z; Bs[buf][ca+3][lr] = rb0.w;                      \
    Bs[buf][ca+0][lr+32] = rb1.x; Bs[buf][ca+1][lr+32] = rb1.y;                \
    Bs[buf][ca+2][lr+32] = rb1.z; Bs[buf][ca+3][lr+32] = rb1.w;

  float acc[4][4] = {};
  int nc = K/32;
  LDG_CHUNK(0); STS_CHUNK(0);
  __syncthreads();
  for (int c = 0; c < nc; c++) {
    if (c+1 < nc) { LDG_CHUNK((c+1)*32); }
    int buf = c & 1;
    #pragma unroll
    for (int k = 0; k < 32; k++) {
      float4 a4 = *(const float4*)&As[buf][k][ty*4];
      float4 b4 = *(const float4*)&Bs[buf][k][tx*4];
      acc[0][0] += a4.x*b4.x; acc[0][1] += a4.x*b4.y; acc[0][2] += a4.x*b4.z; acc[0][3] += a4.x*b4.w;
      acc[1][0] += a4.y*b4.x; acc[1][1] += a4.y*b4.y; acc[1][2] += a4.y*b4.z; acc[1][3] += a4.y*b4.w;
      acc[2][0] += a4.z*b4.x; acc[2][1] += a4.z*b4.y; acc[2][2] += a4.z*b4.z; acc[2][3] += a4.z*b4.w;
      acc[3][0] += a4.w*b4.x; acc[3][1] += a4.w*b4.y; acc[3][2] += a4.w*b4.z; acc[3][3] += a4.w*b4.w;
    }
    if (c+1 < nc) { STS_CHUNK((c+1)&1); }
    __syncthreads();
  }
  #pragma unroll
  for (int i = 0; i < 4; i++) {
    int mm = m0 + ty*4 + i;
    #pragma unroll
    for (int j = 0; j < 4; j++) {
      int nn = n0 + tx*4 + j;
      if (nn < Ncols) {
        float v = acc[i][j];
        if (ATOMIC) {
          atomicAdd(&C[mm*ldc + nn], v);
        } else {
          if (bias) v += bias[nn];
          if (ACT) v = fmaxf(v, 0.f);
          C[mm*ldc + nn] = v;
        }
      }
    }
  }
  #undef LDG_CHUNK
  #undef STS_CHUNK
}

// ---------------- scatter (optional) + edge alpha ----------------
__global__ void k_scat_alpha(const int* __restrict__ esrc, const int* __restrict__ edst,
                             const float* __restrict__ eattr,
                             int w1off, const float* __restrict__ attl, int doScatter) {
  int tid = threadIdx.x;
  if (doScatter) {
    int e = blockIdx.x*256 + tid;
    if (e < Ee) {
      int p = atomicAdd(&g_cur[edst[e]], 1);
      g_perm[p] = e;
    }
  }
  int lane = tid & 31;
  int gw = blockIdx.x*8 + (tid >> 5);
  const float4* xw4 = (const float4*)g_xWr;
  float4 wv = ((const float4*)(g_w1e + w1off))[lane];
  float4 av = ((const float4*)attl)[lane];
  for (int e = gw; e < Ee; e += 2048*8) {
    int src = esrc[e];
    float ea = eattr[e];
    float4 xv = xw4[src*34 + lane];
    float p = lrelu(xv.x + ea*wv.x)*av.x + lrelu(xv.y + ea*wv.y)*av.y
            + lrelu(xv.z + ea*wv.z)*av.z + lrelu(xv.w + ea*wv.w)*av.w;
    #pragma unroll
    for (int s = 16; s > 0; s >>= 1) p += __shfl_xor_sync(0xffffffffu, p, s);
    if (lane == 0) {
      int dst = edst[e];
      float ev = __expf(lrelu(p + g_xWr[dst*136 + 128]));
      g_ealpha[e] = ev;
      atomicAdd(&g_den[dst], ev);
    }
  }
}

// ---------------- per-dst weighted aggregation (restores den=0) --------------
__global__ void k_aggr(const int* __restrict__ esrc, const float* __restrict__ eattr,
                       int w1off) {
  int n = blockIdx.x, tid = threadIdx.x;  // 256 threads
  int begin = g_off[n], cnt = g_off[n+1] - begin;
  __shared__ float s_inv;
  if (tid == 0) { s_inv = 1.f/(g_den[n] + 1e-16f); g_den[n] = 0.f; }
  __syncthreads();
  float inv = s_inv;
  int w = tid >> 5, g = tid & 31;
  const float4* xw4 = (const float4*)g_xWr;
  float4 wv = ((const float4*)(g_w1e + w1off))[g];
  float ax=0.f, ay=0.f, az=0.f, aw=0.f;
  for (int j0 = 0; j0 < cnt; j0 += 8) {
    int j = j0 + w;
    if (j < cnt) {
      int e = g_perm[begin+j];
      float wt = g_ealpha[e]*inv;
      float ea = eattr[e];
      float4 xv = xw4[esrc[e]*34 + g];
      ax += wt*lrelu(xv.x + ea*wv.x);
      ay += wt*lrelu(xv.y + ea*wv.y);
      az += wt*lrelu(xv.z + ea*wv.z);
      aw += wt*lrelu(xv.w + ea*wv.w);
    }
  }
  __shared__ float4 red4[256];
  red4[tid] = make_float4(ax, ay, az, aw);
  __syncthreads();
  if (w == 0) {
    float4 r = red4[g];
    #pragma unroll
    for (int s = 1; s < 8; s++) {
      float4 o = red4[s*32 + g];
      r.x += o.x; r.y += o.y; r.z += o.z; r.w += o.w;
    }
    ((float4*)g_S)[n*32 + g] = r;
  }
}

// ---------------- fused pairwise MLP + masked row softmax ----------------
__global__ void k_final(const float* __restrict__ b1, const float* __restrict__ W2,
                        const float* __restrict__ b2, const float* __restrict__ m,
                        float* __restrict__ out) {
  __shared__ float ash[8][20];
  __shared__ float w2s[20];
  __shared__ float rowM[8], rowInv[8];
  __shared__ __align__(16) float btile[256][21];   // reused as float2[8][256] later
  int tid = threadIdx.x;
  int i0 = blockIdx.x * 8;
  if (tid < 160) {
    int r = tid / 20, c = tid - r*20;
    ash[r][c] = g_ab[(i0+r)*40 + c] + b1[c];
  }
  if (tid < 20) w2s[tid] = W2[tid];
  float b2v = b2[0];
  float omax[8], osum[8];
  #pragma unroll
  for (int r = 0; r < 8; r++) { omax[r] = -1e30f; osum[r] = 0.f; }

  for (int jt = 0; jt < Nn; jt += 256) {
    __syncthreads();
    #pragma unroll
    for (int u = 0; u < 20; u++) {
      int l = u*256 + tid;
      int t = l / 20, c = l - t*20;
      btile[t][c] = g_ab[(jt+t)*40 + 20 + c];
    }
    __syncthreads();
    int j = jt + tid;
    float bl[20];
    #pragma unroll
    for (int c = 0; c < 20; c++) bl[c] = btile[tid][c];
    #pragma unroll
    for (int r = 0; r < 8; r++) {
      float acc = 0.f;
      #pragma unroll
      for (int c = 0; c < 20; c++) acc += fmaxf(ash[r][c] + bl[c], 0.f) * w2s[c];
      size_t idx = (size_t)(i0+r)*Nn + j;
      float lv = (acc + b2v) * m[idx];
      out[idx] = lv;
      float nm = fmaxf(omax[r], lv);
      osum[r] = osum[r]*__expf(omax[r]-nm) + __expf(lv-nm);
      omax[r] = nm;
    }
  }
  // (max,sum) merge: smem transpose + warp reduction (2 syncs)
  __syncthreads();
  float2* pr = (float2*)btile;
  #pragma unroll
  for (int r = 0; r < 8; r++) pr[r*256 + tid] = make_float2(omax[r], osum[r]);
  __syncthreads();
  int w = tid >> 5, lane = tid & 31;
  if (w < 8) {
    float M = -1e30f, S = 0.f;
    #pragma unroll
    for (int i = 0; i < 8; i++) {
      float2 v = pr[w*256 + lane + i*32];
      float nm = fmaxf(M, v.x);
      S = S*__expf(M-nm) + v.y*__expf(v.x-nm);
      M = nm;
    }
    #pragma unroll
    for (int s = 16; s > 0; s >>= 1) {
      float oM = __shfl_xor_sync(0xffffffffu, M, s);
      float oS = __shfl_xor_sync(0xffffffffu, S, s);
      float nm = fmaxf(M, oM);
      S = S*__expf(M-nm) + oS*__expf(oM-nm);
      M = nm;
    }
    if (lane == 0) { rowM[w] = M; rowInv[w] = 1.f/S; }
  }
  __syncthreads();
  for (int jt = 0; jt < Nn; jt += 256) {
    int j = jt + tid;
    #pragma unroll
    for (int r = 0; r < 8; r++) {
      size_t idx = (size_t)(i0+r)*Nn + j;
      out[idx] = __expf(out[idx] - rowM[r]) * rowInv[r];
    }
  }
}

// ---------------- driver ----------------
extern "C" void kernel_launch(void* const* d_in, const int* in_sizes, int n_in,
                              void* d_out, int out_size) {
  const int*   node_ids = (const int*)  d_in[0];
  const int*   eidx     = (const int*)  d_in[1];
  const float* eattr    = (const float*)d_in[2];
  const float* m        = (const float*)d_in[3];
  const float* emb      = (const float*)d_in[4];
  const float* l0_lin1  = (const float*)d_in[5];
  const float* l0_lin2  = (const float*)d_in[6];
  const float* l0_attl  = (const float*)d_in[7];
  const float* l0_attr  = (const float*)d_in[8];
  const float* l0_bias  = (const float*)d_in[9];
  const float* l1_lin1  = (const float*)d_in[10];
  const float* l1_lin2  = (const float*)d_in[11];
  const float* l1_attl  = (const float*)d_in[12];
  const float* l1_attr  = (const float*)d_in[13];
  const float* l1_bias  = (const float*)d_in[14];
  const float* W1       = (const float*)d_in[15];
  const float* b1       = (const float*)d_in[16];
  const float* W2       = (const float*)d_in[17];
  const float* b2       = (const float*)d_in[18];
  float* out = (float*)d_out;
  const int* esrc = eidx;
  const int* edst = eidx + Ee;

  k_setup<<<1237, 256>>>(node_ids, emb, W1, l0_lin1, l1_lin1, l0_attr, l1_attr, edst);

  // xW0 (96 tiles) + CSR scan (block 96)
  k_gemm<0,0><<<97, 256>>>(0, 0, 320, 4, nullptr, 64, nullptr, 2, 0, 136,
                           129, 64, 32, 96, 1);
  k_scat_alpha<<<2048, 256>>>(esrc, edst, eattr, 0, l0_attl, 1);
  k_aggr<<<Nn, 256>>>(esrc, eattr, 0);
  k_gemm<1,0><<<64, 256>>>(1, 0, 128, -1, l0_lin2, 128, l0_bias, 0, 64, 320,
                           128, 128, 32, 64, 0);          // h1 -> feat cols 64..191
  k_gemm<0,0><<<96, 256>>>(0, 64, 320, 5, nullptr, 128, nullptr, 2, 0, 136,
                           129, 128, 32, 96, 0);          // xW1
  k_scat_alpha<<<2048, 256>>>(esrc, edst, eattr, 128, l1_attl, 0);
  k_aggr<<<Nn, 256>>>(esrc, eattr, 128);
  k_gemm<1,0><<<64, 256>>>(1, 0, 128, -1, l1_lin2, 128, l1_bias, 0, 192, 320,
                           128, 128, 32, 64, 0);          // h2 -> feat cols 192..319
  // ab split-K: grid (32 Mtiles, 5 K-chunks), atomicAdd into zeroed g_ab
  k_gemm<0,1><<<dim3(32, 5), 256>>>(0, 0, 320, 3, nullptr, 320, nullptr, 6, 0, 40,
                                    40, 64, 32, 32, 0);
  k_final<<<Nn/8, 256>>>(b1, W2, b2, m, out);
}

// round 6
// speedup vs baseline: 2.5060x; 1.0075x over previous
#include <cuda_runtime.h>

#define Nn 2048
#define Ee 65536

// ---------------- scratch (device globals; no allocations) ----------------
__device__ __align__(16) float g_feat[Nn*320];     // [x | h1 | h2]
__device__ __align__(16) float g_xWr[Nn*136];      // cols 0..127 = xW, col 128 = xr
__device__ __align__(16) float g_S[Nn*128];
__device__ __align__(16) float g_ab[Nn*40];        // zeroed in setup (split-K atomics)
__device__ __align__(16) float g_W1p[40*320];
__device__ __align__(16) float g_B0p[129*64];
__device__ __align__(16) float g_B1p[129*128];
__device__ __align__(16) float g_w1e[256];
__device__ int g_deg[Nn];                          // invariant: zero (restored by scan)
__device__ int g_off[Nn+1];
__device__ int g_cur[Nn];
__device__ int g_perm[Ee];

__device__ __forceinline__ float lrelu(float x) { return x > 0.f ? x : 0.01f*x; }

__device__ __forceinline__ float* sel_ptr(int s) {
  switch (s) {
    case 0: return g_feat;
    case 1: return g_S;
    case 2: return g_xWr;
    case 3: return g_W1p;
    case 4: return g_B0p;
    case 5: return g_B1p;
    case 6: return g_ab;
    default: return nullptr;
  }
}

// ---------------- fused setup: embed + packs + hist + ab-zero ----------------
__global__ void k_setup(const int* __restrict__ ids, const float* __restrict__ emb,
                        const float* __restrict__ W1,
                        const float* __restrict__ l0_lin1, const float* __restrict__ l1_lin1,
                        const float* __restrict__ l0_attr, const float* __restrict__ l1_attr,
                        const int* __restrict__ edst) {
  int b = blockIdx.x, tid = threadIdx.x;
  if (b < 512) {
    int node = b*4 + (tid >> 6);
    int col = tid & 63;
    g_feat[node*320 + col] = emb[ids[node]*64 + col];
  } else if (b < 562) {
    int i = (b-512)*256 + tid;
    if (i < 40*320) {
      int r = i/320, c = i - r*320;
      g_W1p[i] = (r < 20) ? W1[r*640 + c] : W1[(r-20)*640 + 320 + c];
    }
  } else if (b == 562) {
    if (tid < 128) {
      g_w1e[tid]       = l0_lin1[tid*65  + 64];
      g_w1e[128 + tid] = l1_lin1[tid*129 + 128];
    }
  } else if (b < 596) {
    int i = (b-563)*256 + tid;
    if (i < 129*64) {
      int r = i >> 6, c = i & 63;
      g_B0p[i] = (r < 128) ? l0_lin1[r*65 + c] : l0_attr[c];
    }
  } else if (b < 661) {
    int i = (b-596)*256 + tid;
    if (i < 129*128) {
      int r = i >> 7, c = i & 127;
      g_B1p[i] = (r < 128) ? l1_lin1[r*129 + c] : l1_attr[c];
    }
  } else if (b < 917) {
    int e = (b-661)*256 + tid;
    atomicAdd(&g_deg[edst[e]], 1);
  } else {
    g_ab[(b-917)*256 + tid] = 0.f;     // 320 blocks: 81920 floats
  }
}

// ---------------- scan (256 threads), restores g_deg=0 ----------------
__device__ void dev_scan() {
  __shared__ int sw[8];
  int tid = threadIdx.x;
  int base = tid*8;
  int v[8], run = 0;
  #pragma unroll
  for (int i = 0; i < 8; i++) { v[i] = g_deg[base+i]; run += v[i]; }
  int lane = tid & 31, wid = tid >> 5;
  int incl = run;
  #pragma unroll
  for (int o = 1; o < 32; o <<= 1) {
    int u = __shfl_up_sync(0xffffffffu, incl, o);
    if (lane >= o) incl += u;
  }
  if (lane == 31) sw[wid] = incl;
  __syncthreads();
  if (tid == 0) {
    int acc = 0;
    #pragma unroll
    for (int w = 0; w < 8; w++) { int x = sw[w]; sw[w] = acc; acc += x; }
  }
  __syncthreads();
  int off = sw[wid] + incl - run;
  #pragma unroll
  for (int i = 0; i < 8; i++) {
    g_off[base+i] = off; g_cur[base+i] = off;
    off += v[i];
    g_deg[base+i] = 0;
  }
  if (tid == 0) g_off[2048] = Ee;
}

// ---------------- double-buffered 64x64 GEMM: C = act(A @ B^T + bias) --------
template<int ACT, int ATOMIC>
__global__ void __launch_bounds__(256)
k_gemm(int Asel, int aoff, int lda, int Bsel, const float* __restrict__ Bext, int ldb,
       const float* __restrict__ bias, int Csel, int coff, int ldc,
       int Ncols, int K, int nMt, int ntiles, int withScan) {
  if (withScan && (int)blockIdx.x == ntiles) { dev_scan(); return; }
  if ((int)blockIdx.x >= ntiles) return;
  __shared__ __align__(16) float As[2][32][68];
  __shared__ __align__(16) float Bs[2][32][68];
  int koff = blockIdx.y * 64;
  const float* A = sel_ptr(Asel) + aoff + koff;
  const float* B = (Bsel >= 0 ? sel_ptr(Bsel) : Bext) + koff;
  float* C = sel_ptr(Csel) + coff;
  int tid = threadIdx.x;
  int tx = tid & 15, ty = tid >> 4;
  int tile = blockIdx.x;
  int m0 = (tile % nMt)*64, n0 = (tile / nMt)*64;
  int lr = tid >> 3;            // 0..31
  int ca = (tid & 7)*4;
  int rn0 = n0 + lr, rn1 = rn0 + 32;
  float4 ra0, ra1, rb0, rb1;
  const float4 z4 = make_float4(0.f,0.f,0.f,0.f);

  #define LDG_CHUNK(k0)                                                        \
    ra0 = *(const float4*)&A[(m0+lr)*lda + (k0) + ca];                         \
    ra1 = *(const float4*)&A[(m0+lr+32)*lda + (k0) + ca];                      \
    rb0 = (rn0 < Ncols) ? *(const float4*)&B[rn0*ldb + (k0) + ca] : z4;        \
    rb1 = (rn1 < Ncols) ? *(const float4*)&B[rn1*ldb + (k0) + ca] : z4;

  #define STS_CHUNK(buf)                                                       \
    As[buf][ca+0][lr] = ra0.x; As[buf][ca+1][lr] = ra0.y;                      \
    As[buf][ca+2][lr] = ra0.z; As[buf][ca+3][lr] = ra0.w;                      \
    As[buf][ca+0][lr+32] = ra1.x; As[buf][ca+1][lr+32] = ra1.y;                \
    As[buf][ca+2][lr+32] = ra1.z; As[buf][ca+3][lr+32] = ra1.w;                \
    Bs[buf][ca+0][lr] = rb0.x; Bs[buf][ca+1][lr] = rb0.y;                      \
    Bs[buf][ca+2][lr] = rb0.z; Bs[buf][ca+3][lr] = rb0.w;                      \
    Bs[buf][ca+0][lr+32] = rb1.x; Bs[buf][ca+1][lr+32] = rb1.y;                \
    Bs[buf][ca+2][lr+32] = rb1.z; Bs[buf][ca+3][lr+32] = rb1.w;

  float acc[4][4] = {};
  int nc = K/32;
  LDG_CHUNK(0); STS_CHUNK(0);
  __syncthreads();
  for (int c = 0; c < nc; c++) {
    if (c+1 < nc) { LDG_CHUNK((c+1)*32); }
    int buf = c & 1;
    #pragma unroll
    for (int k = 0; k < 32; k++) {
      float4 a4 = *(const float4*)&As[buf][k][ty*4];
      float4 b4 = *(const float4*)&Bs[buf][k][tx*4];
      acc[0][0] += a4.x*b4.x; acc[0][1] += a4.x*b4.y; acc[0][2] += a4.x*b4.z; acc[0][3] += a4.x*b4.w;
      acc[1][0] += a4.y*b4.x; acc[1][1] += a4.y*b4.y; acc[1][2] += a4.y*b4.z; acc[1][3] += a4.y*b4.w;
      acc[2][0] += a4.z*b4.x; acc[2][1] += a4.z*b4.y; acc[2][2] += a4.z*b4.z; acc[2][3] += a4.z*b4.w;
      acc[3][0] += a4.w*b4.x; acc[3][1] += a4.w*b4.y; acc[3][2] += a4.w*b4.z; acc[3][3] += a4.w*b4.w;
    }
    if (c+1 < nc) { STS_CHUNK((c+1)&1); }
    __syncthreads();
  }
  #pragma unroll
  for (int i = 0; i < 4; i++) {
    int mm = m0 + ty*4 + i;
    #pragma unroll
    for (int j = 0; j < 4; j++) {
      int nn = n0 + tx*4 + j;
      if (nn < Ncols) {
        float v = acc[i][j];
        if (ATOMIC) {
          atomicAdd(&C[mm*ldc + nn], v);
        } else {
          if (bias) v += bias[nn];
          if (ACT) v = fmaxf(v, 0.f);
          C[mm*ldc + nn] = v;
        }
      }
    }
  }
  #undef LDG_CHUNK
  #undef STS_CHUNK
}

// ---------------- CSR scatter ----------------
__global__ void k_scatter(const int* __restrict__ edst) {
  int e = blockIdx.x*256 + threadIdx.x;
  int p = atomicAdd(&g_cur[edst[e]], 1);
  g_perm[p] = e;
}

// ---------------- single-pass edge attention + aggregation ----------------
// S[n] = (sum_e ev_e * h_e) / (sum_e ev_e + 1e-16),
//   h_e = lrelu(xW[src] + ea*w1e), ev_e = exp(lrelu(h_e.att_l + xr[n]))
__global__ void __launch_bounds__(256)
k_aggr(const int* __restrict__ esrc, const float* __restrict__ eattr,
       int w1off, const float* __restrict__ attl) {
  int n = blockIdx.x, tid = threadIdx.x;  // 256 threads, 8 warps
  int begin = g_off[n], cnt = g_off[n+1] - begin;
  int w = tid >> 5, lane = tid & 31;
  const float4* xw4 = (const float4*)g_xWr;
  float4 wv = ((const float4*)(g_w1e + w1off))[lane];
  float4 av = ((const float4*)attl)[lane];
  float xr = g_xWr[n*136 + 128];
  float ax=0.f, ay=0.f, az=0.f, aw=0.f, den=0.f;
  for (int j0 = 0; j0 < cnt; j0 += 8) {
    int j = j0 + w;
    if (j < cnt) {                       // uniform across warp (depends on w only)
      int e = g_perm[begin+j];
      float ea = eattr[e];
      float4 xv = xw4[esrc[e]*34 + lane];
      float hx = lrelu(xv.x + ea*wv.x);
      float hy = lrelu(xv.y + ea*wv.y);
      float hz = lrelu(xv.z + ea*wv.z);
      float hw = lrelu(xv.w + ea*wv.w);
      float p = hx*av.x + hy*av.y + hz*av.z + hw*av.w;
      #pragma unroll
      for (int s = 16; s > 0; s >>= 1) p += __shfl_xor_sync(0xffffffffu, p, s);
      float ev = __expf(lrelu(p + xr));  // all lanes hold the same value
      ax += ev*hx; ay += ev*hy; az += ev*hz; aw += ev*hw;
      den += ev;                         // per-lane copy of the warp's denominator
    }
  }
  __shared__ float4 red4[256];
  __shared__ float dred[8];
  red4[tid] = make_float4(ax, ay, az, aw);
  if (lane == 0) dred[w] = den;
  __syncthreads();
  if (w == 0) {
    float4 r = red4[lane];
    #pragma unroll
    for (int s = 1; s < 8; s++) {
      float4 o = red4[s*32 + lane];
      r.x += o.x; r.y += o.y; r.z += o.z; r.w += o.w;
    }
    float d = 0.f;
    #pragma unroll
    for (int s = 0; s < 8; s++) d += dred[s];
    float inv = 1.f/(d + 1e-16f);
    r.x *= inv; r.y *= inv; r.z *= inv; r.w *= inv;
    ((float4*)g_S)[n*32 + lane] = r;
  }
}

// ---------------- fused pairwise MLP + masked row softmax (reg-resident) -----
__global__ void __launch_bounds__(256)
k_final(const float* __restrict__ b1, const float* __restrict__ W2,
        const float* __restrict__ b2, const float* __restrict__ m,
        float* __restrict__ out) {
  __shared__ float ash[8][20];
  __shared__ float w2s[20];
  __shared__ float rowM[8], rowInv[8];
  __shared__ __align__(16) float btile[256][21];   // reused as float2[8][256] later
  int tid = threadIdx.x;
  int i0 = blockIdx.x * 8;
  if (tid < 160) {
    int r = tid / 20, c = tid - r*20;
    ash[r][c] = g_ab[(i0+r)*40 + c] + b1[c];
  }
  if (tid < 20) w2s[tid] = W2[tid];
  float b2v = b2[0];
  float lreg[8][8];                                // [tile][row] raw logits
  float omax[8], osum[8];
  #pragma unroll
  for (int r = 0; r < 8; r++) { omax[r] = -1e30f; osum[r] = 0.f; }

  #pragma unroll
  for (int t = 0; t < 8; t++) {
    int jt = t*256;
    __syncthreads();
    #pragma unroll
    for (int u = 0; u < 20; u++) {
      int l = u*256 + tid;
      int tt = l / 20, c = l - tt*20;
      btile[tt][c] = g_ab[(jt+tt)*40 + 20 + c];
    }
    __syncthreads();
    int j = jt + tid;
    float bl[20];
    #pragma unroll
    for (int c = 0; c < 20; c++) bl[c] = btile[tid][c];
    #pragma unroll
    for (int r = 0; r < 8; r++) {
      float acc = 0.f;
      #pragma unroll
      for (int c = 0; c < 20; c++) acc += fmaxf(ash[r][c] + bl[c], 0.f) * w2s[c];
      float lv = (acc + b2v) * m[(size_t)(i0+r)*Nn + j];
      lreg[t][r] = lv;
      float nm = fmaxf(omax[r], lv);
      osum[r] = osum[r]*__expf(omax[r]-nm) + __expf(lv-nm);
      omax[r] = nm;
    }
  }
  // (max,sum) merge: smem transpose + warp reduction (2 syncs)
  __syncthreads();
  float2* pr = (float2*)btile;
  #pragma unroll
  for (int r = 0; r < 8; r++) pr[r*256 + tid] = make_float2(omax[r], osum[r]);
  __syncthreads();
  int w = tid >> 5, lane = tid & 31;
  if (w < 8) {
    float M = -1e30f, S = 0.f;
    #pragma unroll
    for (int i = 0; i < 8; i++) {
      float2 v = pr[w*256 + lane + i*32];
      float nm = fmaxf(M, v.x);
      S = S*__expf(M-nm) + v.y*__expf(v.x-nm);
      M = nm;
    }
    #pragma unroll
    for (int s = 16; s > 0; s >>= 1) {
      float oM = __shfl_xor_sync(0xffffffffu, M, s);
      float oS = __shfl_xor_sync(0xffffffffu, S, s);
      float nm = fmaxf(M, oM);
      S = S*__expf(M-nm) + oS*__expf(oM-nm);
      M = nm;
    }
    if (lane == 0) { rowM[w] = M; rowInv[w] = 1.f/S; }
  }
  __syncthreads();
  #pragma unroll
  for (int t = 0; t < 8; t++) {
    int j = t*256 + tid;
    #pragma unroll
    for (int r = 0; r < 8; r++) {
      out[(size_t)(i0+r)*Nn + j] = __expf(lreg[t][r] - rowM[r]) * rowInv[r];
    }
  }
}

// ---------------- driver ----------------
extern "C" void kernel_launch(void* const* d_in, const int* in_sizes, int n_in,
                              void* d_out, int out_size) {
  const int*   node_ids = (const int*)  d_in[0];
  const int*   eidx     = (const int*)  d_in[1];
  const float* eattr    = (const float*)d_in[2];
  const float* m        = (const float*)d_in[3];
  const float* emb      = (const float*)d_in[4];
  const float* l0_lin1  = (const float*)d_in[5];
  const float* l0_lin2  = (const float*)d_in[6];
  const float* l0_attl  = (const float*)d_in[7];
  const float* l0_attr  = (const float*)d_in[8];
  const float* l0_bias  = (const float*)d_in[9];
  const float* l1_lin1  = (const float*)d_in[10];
  const float* l1_lin2  = (const float*)d_in[11];
  const float* l1_attl  = (const float*)d_in[12];
  const float* l1_attr  = (const float*)d_in[13];
  const float* l1_bias  = (const float*)d_in[14];
  const float* W1       = (const float*)d_in[15];
  const float* b1       = (const float*)d_in[16];
  const float* W2       = (const float*)d_in[17];
  const float* b2       = (const float*)d_in[18];
  float* out = (float*)d_out;
  const int* esrc = eidx;
  const int* edst = eidx + Ee;

  k_setup<<<1237, 256>>>(node_ids, emb, W1, l0_lin1, l1_lin1, l0_attr, l1_attr, edst);

  // xW0 (96 tiles) + CSR scan (block 96)
  k_gemm<0,0><<<97, 256>>>(0, 0, 320, 4, nullptr, 64, nullptr, 2, 0, 136,
                           129, 64, 32, 96, 1);
  k_scatter<<<Ee/256, 256>>>(edst);
  k_aggr<<<Nn, 256>>>(esrc, eattr, 0, l0_attl);
  k_gemm<1,0><<<64, 256>>>(1, 0, 128, -1, l0_lin2, 128, l0_bias, 0, 64, 320,
                           128, 128, 32, 64, 0);          // h1 -> feat cols 64..191
  k_gemm<0,0><<<96, 256>>>(0, 64, 320, 5, nullptr, 128, nullptr, 2, 0, 136,
                           129, 128, 32, 96, 0);          // xW1
  k_aggr<<<Nn, 256>>>(esrc, eattr, 128, l1_attl);
  k_gemm<1,0><<<64, 256>>>(1, 0, 128, -1, l1_lin2, 128, l1_bias, 0, 192, 320,
                           128, 128, 32, 64, 0);          // h2 -> feat cols 192..319
  // ab split-K: grid (32 Mtiles, 5 K-chunks), atomicAdd into zeroed g_ab
  k_gemm<0,1><<<dim3(32, 5), 256>>>(0, 0, 320, 3, nullptr, 320, nullptr, 6, 0, 40,
                                    40, 64, 32, 32, 0);
  k_final<<<Nn/8, 256>>>(b1, W2, b2, m, out);
}

// round 7
// speedup vs baseline: 2.5801x; 1.0296x over previous
#include <cuda_runtime.h>

#define Nn 2048
#define Ee 65536

// ---------------- scratch (device globals; no allocations) ----------------
__device__ __align__(16) float g_feat[Nn*320];     // [x | h1 | h2]
__device__ __align__(16) float g_xWr[Nn*136];      // cols 0..127 = xW, col 128 = xr
__device__ __align__(16) float g_S[Nn*128];
__device__ __align__(16) float g_ab[Nn*40];        // zeroed in setup (split-K atomics)
__device__ __align__(16) float g_W1p[40*320];
__device__ __align__(16) float g_B0p[129*64];
__device__ __align__(16) float g_B1p[129*128];
__device__ __align__(16) float g_w1e[256];
__device__ __align__(16) float2 g_edge[Ee];        // CSR payload: (src bits, edge_attr)
__device__ int g_deg[Nn];                          // invariant: zero (restored by scan)
__device__ int g_off[Nn+1];
__device__ int g_cur[Nn];

__device__ __forceinline__ float lrelu(float x) { return x > 0.f ? x : 0.01f*x; }

__device__ __forceinline__ float* sel_ptr(int s) {
  switch (s) {
    case 0: return g_feat;
    case 1: return g_S;
    case 2: return g_xWr;
    case 3: return g_W1p;
    case 4: return g_B0p;
    case 5: return g_B1p;
    case 6: return g_ab;
    default: return nullptr;
  }
}

// ---------------- fused setup: embed + packs + hist + ab-zero ----------------
__global__ void k_setup(const int* __restrict__ ids, const float* __restrict__ emb,
                        const float* __restrict__ W1,
                        const float* __restrict__ l0_lin1, const float* __restrict__ l1_lin1,
                        const float* __restrict__ l0_attr, const float* __restrict__ l1_attr,
                        const int* __restrict__ edst) {
  int b = blockIdx.x, tid = threadIdx.x;
  if (b < 512) {
    int node = b*4 + (tid >> 6);
    int col = tid & 63;
    g_feat[node*320 + col] = emb[ids[node]*64 + col];
  } else if (b < 562) {
    int i = (b-512)*256 + tid;
    if (i < 40*320) {
      int r = i/320, c = i - r*320;
      g_W1p[i] = (r < 20) ? W1[r*640 + c] : W1[(r-20)*640 + 320 + c];
    }
  } else if (b == 562) {
    if (tid < 128) {
      g_w1e[tid]       = l0_lin1[tid*65  + 64];
      g_w1e[128 + tid] = l1_lin1[tid*129 + 128];
    }
  } else if (b < 596) {
    int i = (b-563)*256 + tid;
    if (i < 129*64) {
      int r = i >> 6, c = i & 63;
      g_B0p[i] = (r < 128) ? l0_lin1[r*65 + c] : l0_attr[c];
    }
  } else if (b < 661) {
    int i = (b-596)*256 + tid;
    if (i < 129*128) {
      int r = i >> 7, c = i & 127;
      g_B1p[i] = (r < 128) ? l1_lin1[r*129 + c] : l1_attr[c];
    }
  } else if (b < 917) {
    int e = (b-661)*256 + tid;
    atomicAdd(&g_deg[edst[e]], 1);
  } else {
    g_ab[(b-917)*256 + tid] = 0.f;     // 320 blocks: 81920 floats
  }
}

// ---------------- scan (256 threads), restores g_deg=0 ----------------
__device__ void dev_scan() {
  __shared__ int sw[8];
  int tid = threadIdx.x;
  int base = tid*8;
  int v[8], run = 0;
  #pragma unroll
  for (int i = 0; i < 8; i++) { v[i] = g_deg[base+i]; run += v[i]; }
  int lane = tid & 31, wid = tid >> 5;
  int incl = run;
  #pragma unroll
  for (int o = 1; o < 32; o <<= 1) {
    int u = __shfl_up_sync(0xffffffffu, incl, o);
    if (lane >= o) incl += u;
  }
  if (lane == 31) sw[wid] = incl;
  __syncthreads();
  if (tid == 0) {
    int acc = 0;
    #pragma unroll
    for (int w = 0; w < 8; w++) { int x = sw[w]; sw[w] = acc; acc += x; }
  }
  __syncthreads();
  int off = sw[wid] + incl - run;
  #pragma unroll
  for (int i = 0; i < 8; i++) {
    g_off[base+i] = off; g_cur[base+i] = off;
    off += v[i];
    g_deg[base+i] = 0;
  }
  if (tid == 0) g_off[2048] = Ee;
}

// ---------------- double-buffered 64x64 GEMM: C = act(A @ B^T + bias) --------
template<int ACT, int ATOMIC>
__global__ void __launch_bounds__(256)
k_gemm(int Asel, int aoff, int lda, int Bsel, const float* __restrict__ Bext, int ldb,
       const float* __restrict__ bias, int Csel, int coff, int ldc,
       int Ncols, int K, int nMt, int ntiles, int withScan) {
  if (withScan && (int)blockIdx.x == ntiles) { dev_scan(); return; }
  if ((int)blockIdx.x >= ntiles) return;
  __shared__ __align__(16) float As[2][32][68];
  __shared__ __align__(16) float Bs[2][32][68];
  int koff = blockIdx.y * 64;
  const float* A = sel_ptr(Asel) + aoff + koff;
  const float* B = (Bsel >= 0 ? sel_ptr(Bsel) : Bext) + koff;
  float* C = sel_ptr(Csel) + coff;
  int tid = threadIdx.x;
  int tx = tid & 15, ty = tid >> 4;
  int tile = blockIdx.x;
  int m0 = (tile % nMt)*64, n0 = (tile / nMt)*64;
  int lr = tid >> 3;            // 0..31
  int ca = (tid & 7)*4;
  int rn0 = n0 + lr, rn1 = rn0 + 32;
  float4 ra0, ra1, rb0, rb1;
  const float4 z4 = make_float4(0.f,0.f,0.f,0.f);

  #define LDG_CHUNK(k0)                                                        \
    ra0 = *(const float4*)&A[(m0+lr)*lda + (k0) + ca];                         \
    ra1 = *(const float4*)&A[(m0+lr+32)*lda + (k0) + ca];                      \
    rb0 = (rn0 < Ncols) ? *(const float4*)&B[rn0*ldb + (k0) + ca] : z4;        \
    rb1 = (rn1 < Ncols) ? *(const float4*)&B[rn1*ldb + (k0) + ca] : z4;

  #define STS_CHUNK(buf)                                                       \
    As[buf][ca+0][lr] = ra0.x; As[buf][ca+1][lr] = ra0.y;                      \
    As[buf][ca+2][lr] = ra0.z; As[buf][ca+3][lr] = ra0.w;                      \
    As[buf][ca+0][lr+32] = ra1.x; As[buf][ca+1][lr+32] = ra1.y;                \
    As[buf][ca+2][lr+32] = ra1.z; As[buf][ca+3][lr+32] = ra1.w;                \
    Bs[buf][ca+0][lr] = rb0.x; Bs[buf][ca+1][lr] = rb0.y;                      \
    Bs[buf][ca+2][lr] = rb0.z; Bs[buf][ca+3][lr] = rb0.w;                      \
    Bs[buf][ca+0][lr+32] = rb1.x; Bs[buf][ca+1][lr+32] = rb1.y;                \
    Bs[buf][ca+2][lr+32] = rb1.z; Bs[buf][ca+3][lr+32] = rb1.w;

  float acc[4][4] = {};
  int nc = K/32;
  LDG_CHUNK(0); STS_CHUNK(0);
  __syncthreads();
  for (int c = 0; c < nc; c++) {
    if (c+1 < nc) { LDG_CHUNK((c+1)*32); }
    int buf = c & 1;
    #pragma unroll
    for (int k = 0; k < 32; k++) {
      float4 a4 = *(const float4*)&As[buf][k][ty*4];
      float4 b4 = *(const float4*)&Bs[buf][k][tx*4];
      acc[0][0] += a4.x*b4.x; acc[0][1] += a4.x*b4.y; acc[0][2] += a4.x*b4.z; acc[0][3] += a4.x*b4.w;
      acc[1][0] += a4.y*b4.x; acc[1][1] += a4.y*b4.y; acc[1][2] += a4.y*b4.z; acc[1][3] += a4.y*b4.w;
      acc[2][0] += a4.z*b4.x; acc[2][1] += a4.z*b4.y; acc[2][2] += a4.z*b4.z; acc[2][3] += a4.z*b4.w;
      acc[3][0] += a4.w*b4.x; acc[3][1] += a4.w*b4.y; acc[3][2] += a4.w*b4.z; acc[3][3] += a4.w*b4.w;
    }
    if (c+1 < nc) { STS_CHUNK((c+1)&1); }
    __syncthreads();
  }
  #pragma unroll
  for (int i = 0; i < 4; i++) {
    int mm = m0 + ty*4 + i;
    #pragma unroll
    for (int j = 0; j < 4; j++) {
      int nn = n0 + tx*4 + j;
      if (nn < Ncols) {
        float v = acc[i][j];
        if (ATOMIC) {
          atomicAdd(&C[mm*ldc + nn], v);
        } else {
          if (bias) v += bias[nn];
          if (ACT) v = fmaxf(v, 0.f);
          C[mm*ldc + nn] = v;
        }
      }
    }
  }
  #undef LDG_CHUNK
  #undef STS_CHUNK
}

// ---------------- CSR scatter with combined payload ----------------
__global__ void k_scatter(const int* __restrict__ esrc, const int* __restrict__ edst,
                          const float* __restrict__ eattr) {
  int e = blockIdx.x*256 + threadIdx.x;
  int p = atomicAdd(&g_cur[edst[e]], 1);
  g_edge[p] = make_float2(__int_as_float(esrc[e]), eattr[e]);
}

// ---------------- single-pass edge attention + aggregation (4-way ILP) -------
__global__ void __launch_bounds__(256)
k_aggr(int w1off, const float* __restrict__ attl) {
  int n = blockIdx.x, tid = threadIdx.x;  // 256 threads, 8 warps
  int begin = g_off[n], cnt = g_off[n+1] - begin;
  int w = tid >> 5, lane = tid & 31;
  const float4* xw4 = (const float4*)g_xWr;
  float4 wv = ((const float4*)(g_w1e + w1off))[lane];
  float4 av = ((const float4*)attl)[lane];
  float xr = g_xWr[n*136 + 128];
  float ax=0.f, ay=0.f, az=0.f, aw=0.f, den=0.f;
  for (int j0 = 0; j0 < cnt; j0 += 32) {
    bool vv[4]; float2 ee[4]; float4 xx[4];
    float hx[4], hy[4], hz[4], hw[4], pp[4];
    #pragma unroll
    for (int u = 0; u < 4; u++) { vv[u] = (j0 + w + u*8) < cnt; pp[u] = 0.f; }
    #pragma unroll
    for (int u = 0; u < 4; u++) if (vv[u]) ee[u] = g_edge[begin + j0 + w + u*8];
    #pragma unroll
    for (int u = 0; u < 4; u++) if (vv[u]) xx[u] = xw4[__float_as_int(ee[u].x)*34 + lane];
    #pragma unroll
    for (int u = 0; u < 4; u++) if (vv[u]) {
      float ea = ee[u].y;
      hx[u] = lrelu(xx[u].x + ea*wv.x);
      hy[u] = lrelu(xx[u].y + ea*wv.y);
      hz[u] = lrelu(xx[u].z + ea*wv.z);
      hw[u] = lrelu(xx[u].w + ea*wv.w);
      pp[u] = hx[u]*av.x + hy[u]*av.y + hz[u]*av.z + hw[u]*av.w;
    }
    #pragma unroll
    for (int s = 16; s > 0; s >>= 1) {
      #pragma unroll
      for (int u = 0; u < 4; u++) pp[u] += __shfl_xor_sync(0xffffffffu, pp[u], s);
    }
    #pragma unroll
    for (int u = 0; u < 4; u++) if (vv[u]) {
      float ev = __expf(lrelu(pp[u] + xr));
      ax += ev*hx[u]; ay += ev*hy[u]; az += ev*hz[u]; aw += ev*hw[u];
      den += ev;
    }
  }
  __shared__ float4 red4[256];
  __shared__ float dred[8];
  red4[tid] = make_float4(ax, ay, az, aw);
  if (lane == 0) dred[w] = den;
  __syncthreads();
  if (w == 0) {
    float4 r = red4[lane];
    #pragma unroll
    for (int s = 1; s < 8; s++) {
      float4 o = red4[s*32 + lane];
      r.x += o.x; r.y += o.y; r.z += o.z; r.w += o.w;
    }
    float d = 0.f;
    #pragma unroll
    for (int s = 0; s < 8; s++) d += dred[s];
    float inv = 1.f/(d + 1e-16f);
    r.x *= inv; r.y *= inv; r.z *= inv; r.w *= inv;
    ((float4*)g_S)[n*32 + lane] = r;
  }
}

// ---------------- fused pairwise MLP + masked row softmax (f32x2) ------------
__global__ void __launch_bounds__(256)
k_final(const float* __restrict__ b1, const float* __restrict__ W2,
        const float* __restrict__ b2, const float* __restrict__ m,
        float* __restrict__ out) {
  __shared__ unsigned long long ash2[8][10];       // packed (a+b1) col pairs
  __shared__ unsigned long long w2sh[10];
  __shared__ float rowM[8], rowInv[8];
  __shared__ __align__(16) float btile[256][22];   // stride 22 -> aligned b64; reused for reduce
  int tid = threadIdx.x;
  int i0 = blockIdx.x * 8;
  if (tid < 80) {
    int r = tid/10, cp = tid - r*10;
    float a0 = g_ab[(i0+r)*40 + 2*cp]   + b1[2*cp];
    float a1 = g_ab[(i0+r)*40 + 2*cp+1] + b1[2*cp+1];
    asm("mov.b64 %0, {%1, %2};" : "=l"(ash2[r][cp]) : "f"(a0), "f"(a1));
  }
  if (tid < 10) {
    asm("mov.b64 %0, {%1, %2};" : "=l"(w2sh[tid]) : "f"(W2[2*tid]), "f"(W2[2*tid+1]));
  }
  float b2v = b2[0];
  float omax[8], osum[8];
  #pragma unroll
  for (int r = 0; r < 8; r++) { omax[r] = -1e30f; osum[r] = 0.f; }
  __syncthreads();
  unsigned long long wr[10];
  #pragma unroll
  for (int cp = 0; cp < 10; cp++) wr[cp] = w2sh[cp];

  for (int jt = 0; jt < Nn; jt += 256) {
    __syncthreads();
    #pragma unroll
    for (int u = 0; u < 20; u++) {
      int l = u*256 + tid;
      int t = l / 20, c = l - t*20;
      btile[t][c] = g_ab[(jt+t)*40 + 20 + c];
    }
    __syncthreads();
    unsigned long long bl2[10];
    #pragma unroll
    for (int cp = 0; cp < 10; cp++)
      bl2[cp] = *(const unsigned long long*)&btile[tid][2*cp];
    int j = jt + tid;
    #pragma unroll
    for (int r = 0; r < 8; r++) {
      unsigned long long acc2 = 0ULL;      // (0.f, 0.f)
      #pragma unroll
      for (int cp = 0; cp < 10; cp++) {
        unsigned long long s;
        asm("add.rn.f32x2 %0, %1, %2;" : "=l"(s) : "l"(ash2[r][cp]), "l"(bl2[cp]));
        float lo, hi;
        asm("mov.b64 {%0, %1}, %2;" : "=f"(lo), "=f"(hi) : "l"(s));
        lo = fmaxf(lo, 0.f); hi = fmaxf(hi, 0.f);
        asm("mov.b64 %0, {%1, %2};" : "=l"(s) : "f"(lo), "f"(hi));
        asm("fma.rn.f32x2 %0, %1, %2, %3;" : "=l"(acc2) : "l"(s), "l"(wr[cp]), "l"(acc2));
      }
      float alo, ahi;
      asm("mov.b64 {%0, %1}, %2;" : "=f"(alo), "=f"(ahi) : "l"(acc2));
      size_t idx = (size_t)(i0+r)*Nn + j;
      float lv = (alo + ahi + b2v) * m[idx];
      out[idx] = lv;                       // park raw logit (L2-resident)
      float nm = fmaxf(omax[r], lv);
      osum[r] = osum[r]*__expf(omax[r]-nm) + __expf(lv-nm);
      omax[r] = nm;
    }
  }
  // (max,sum) merge: smem transpose + warp reduction (2 syncs)
  __syncthreads();
  float2* pr = (float2*)btile;
  #pragma unroll
  for (int r = 0; r < 8; r++) pr[r*256 + tid] = make_float2(omax[r], osum[r]);
  __syncthreads();
  int w = tid >> 5, lane = tid & 31;
  if (w < 8) {
    float M = -1e30f, S = 0.f;
    #pragma unroll
    for (int i = 0; i < 8; i++) {
      float2 v = pr[w*256 + lane + i*32];
      float nm = fmaxf(M, v.x);
      S = S*__expf(M-nm) + v.y*__expf(v.x-nm);
      M = nm;
    }
    #pragma unroll
    for (int s = 16; s > 0; s >>= 1) {
      float oM = __shfl_xor_sync(0xffffffffu, M, s);
      float oS = __shfl_xor_sync(0xffffffffu, S, s);
      float nm = fmaxf(M, oM);
      S = S*__expf(M-nm) + oS*__expf(oM-nm);
      M = nm;
    }
    if (lane == 0) { rowM[w] = M; rowInv[w] = 1.f/S; }
  }
  __syncthreads();
  for (int jt = 0; jt < Nn; jt += 256) {
    int j = jt + tid;
    #pragma unroll
    for (int r = 0; r < 8; r++) {
      size_t idx = (size_t)(i0+r)*Nn + j;
      out[idx] = __expf(out[idx] - rowM[r]) * rowInv[r];
    }
  }
}

// ---------------- driver ----------------
extern "C" void kernel_launch(void* const* d_in, const int* in_sizes, int n_in,
                              void* d_out, int out_size) {
  const int*   node_ids = (const int*)  d_in[0];
  const int*   eidx     = (const int*)  d_in[1];
  const float* eattr    = (const float*)d_in[2];
  const float* m        = (const float*)d_in[3];
  const float* emb      = (const float*)d_in[4];
  const float* l0_lin1  = (const float*)d_in[5];
  const float* l0_lin2  = (const float*)d_in[6];
  const float* l0_attl  = (const float*)d_in[7];
  const float* l0_attr  = (const float*)d_in[8];
  const float* l0_bias  = (const float*)d_in[9];
  const float* l1_lin1  = (const float*)d_in[10];
  const float* l1_lin2  = (const float*)d_in[11];
  const float* l1_attl  = (const float*)d_in[12];
  const float* l1_attr  = (const float*)d_in[13];
  const float* l1_bias  = (const float*)d_in[14];
  const float* W1       = (const float*)d_in[15];
  const float* b1       = (const float*)d_in[16];
  const float* W2       = (const float*)d_in[17];
  const float* b2       = (const float*)d_in[18];
  float* out = (float*)d_out;
  const int* esrc = eidx;
  const int* edst = eidx + Ee;

  k_setup<<<1237, 256>>>(node_ids, emb, W1, l0_lin1, l1_lin1, l0_attr, l1_attr, edst);

  // xW0 (96 tiles) + CSR scan (block 96)
  k_gemm<0,0><<<97, 256>>>(0, 0, 320, 4, nullptr, 64, nullptr, 2, 0, 136,
                           129, 64, 32, 96, 1);
  k_scatter<<<Ee/256, 256>>>(esrc, edst, eattr);
  k_aggr<<<Nn, 256>>>(0, l0_attl);
  k_gemm<1,0><<<64, 256>>>(1, 0, 128, -1, l0_lin2, 128, l0_bias, 0, 64, 320,
                           128, 128, 32, 64, 0);          // h1 -> feat cols 64..191
  k_gemm<0,0><<<96, 256>>>(0, 64, 320, 5, nullptr, 128, nullptr, 2, 0, 136,
                           129, 128, 32, 96, 0);          // xW1
  k_aggr<<<Nn, 256>>>(128, l1_attl);
  k_gemm<1,0><<<64, 256>>>(1, 0, 128, -1, l1_lin2, 128, l1_bias, 0, 192, 320,
                           128, 128, 32, 64, 0);          // h2 -> feat cols 192..319
  // ab split-K: grid (32 Mtiles, 5 K-chunks), atomicAdd into zeroed g_ab
  k_gemm<0,1><<<dim3(32, 5), 256>>>(0, 0, 320, 3, nullptr, 320, nullptr, 6, 0, 40,
                                    40, 64, 32, 32, 0);
  k_final<<<Nn/8, 256>>>(b1, W2, b2, m, out);
}

// round 8
// speedup vs baseline: 2.5847x; 1.0018x over previous
#include <cuda_runtime.h>

#define Nn 2048
#define Ee 65536

// ---------------- scratch (device globals; no allocations) ----------------
__device__ __align__(16) float g_feat[Nn*320];     // [x | h1 | h2]
__device__ __align__(16) float g_xWr[Nn*136];      // cols 0..127 = xW, col 128 = xr
__device__ __align__(16) float g_S[Nn*128];
__device__ __align__(16) float g_ab[Nn*40];        // zeroed in setup (split-K atomics)
__device__ __align__(16) float g_W1p[40*320];
__device__ __align__(16) float g_B0p[129*64];
__device__ __align__(16) float g_B1p[129*128];
__device__ __align__(16) float g_w1e[256];
__device__ __align__(16) float2 g_edge[Ee];        // CSR payload: (src bits, edge_attr)
__device__ int g_deg[Nn];                          // invariant: zero (restored by scan)
__device__ int g_off[Nn+1];
__device__ int g_cur[Nn];

__device__ __forceinline__ float lrelu(float x) { return x > 0.f ? x : 0.01f*x; }

__device__ __forceinline__ float* sel_ptr(int s) {
  switch (s) {
    case 0: return g_feat;
    case 1: return g_S;
    case 2: return g_xWr;
    case 3: return g_W1p;
    case 4: return g_B0p;
    case 5: return g_B1p;
    case 6: return g_ab;
    default: return nullptr;
  }
}

// ---------------- fused setup: embed + packs + hist + ab-zero ----------------
__global__ void k_setup(const int* __restrict__ ids, const float* __restrict__ emb,
                        const float* __restrict__ W1,
                        const float* __restrict__ l0_lin1, const float* __restrict__ l1_lin1,
                        const float* __restrict__ l0_attr, const float* __restrict__ l1_attr,
                        const int* __restrict__ edst) {
  int b = blockIdx.x, tid = threadIdx.x;
  if (b < 512) {
    int node = b*4 + (tid >> 6);
    int col = tid & 63;
    g_feat[node*320 + col] = emb[ids[node]*64 + col];
  } else if (b < 562) {
    int i = (b-512)*256 + tid;
    if (i < 40*320) {
      int r = i/320, c = i - r*320;
      g_W1p[i] = (r < 20) ? W1[r*640 + c] : W1[(r-20)*640 + 320 + c];
    }
  } else if (b == 562) {
    if (tid < 128) {
      g_w1e[tid]       = l0_lin1[tid*65  + 64];
      g_w1e[128 + tid] = l1_lin1[tid*129 + 128];
    }
  } else if (b < 596) {
    int i = (b-563)*256 + tid;
    if (i < 129*64) {
      int r = i >> 6, c = i & 63;
      g_B0p[i] = (r < 128) ? l0_lin1[r*65 + c] : l0_attr[c];
    }
  } else if (b < 661) {
    int i = (b-596)*256 + tid;
    if (i < 129*128) {
      int r = i >> 7, c = i & 127;
      g_B1p[i] = (r < 128) ? l1_lin1[r*129 + c] : l1_attr[c];
    }
  } else if (b < 917) {
    int e = (b-661)*256 + tid;
    atomicAdd(&g_deg[edst[e]], 1);
  } else {
    g_ab[(b-917)*256 + tid] = 0.f;     // 320 blocks: 81920 floats
  }
}

// ---------------- scan (256 threads), restores g_deg=0 ----------------
__device__ void dev_scan() {
  __shared__ int sw[8];
  int tid = threadIdx.x;
  int base = tid*8;
  int v[8], run = 0;
  #pragma unroll
  for (int i = 0; i < 8; i++) { v[i] = g_deg[base+i]; run += v[i]; }
  int lane = tid & 31, wid = tid >> 5;
  int incl = run;
  #pragma unroll
  for (int o = 1; o < 32; o <<= 1) {
    int u = __shfl_up_sync(0xffffffffu, incl, o);
    if (lane >= o) incl += u;
  }
  if (lane == 31) sw[wid] = incl;
  __syncthreads();
  if (tid == 0) {
    int acc = 0;
    #pragma unroll
    for (int w = 0; w < 8; w++) { int x = sw[w]; sw[w] = acc; acc += x; }
  }
  __syncthreads();
  int off = sw[wid] + incl - run;
  #pragma unroll
  for (int i = 0; i < 8; i++) {
    g_off[base+i] = off; g_cur[base+i] = off;
    off += v[i];
    g_deg[base+i] = 0;
  }
  if (tid == 0) g_off[2048] = Ee;
}

// ---------------- double-buffered 64x64 GEMM: C = act(A @ B^T + bias) --------
template<int ACT, int ATOMIC>
__global__ void __launch_bounds__(256)
k_gemm(int Asel, int aoff, int lda, int Bsel, const float* __restrict__ Bext, int ldb,
       const float* __restrict__ bias, int Csel, int coff, int ldc,
       int Ncols, int K, int nMt, int ntiles, int withScan) {
  if (withScan && (int)blockIdx.x == ntiles) { dev_scan(); return; }
  if ((int)blockIdx.x >= ntiles) return;
  __shared__ __align__(16) float As[2][32][68];
  __shared__ __align__(16) float Bs[2][32][68];
  int koff = blockIdx.y * 64;
  const float* A = sel_ptr(Asel) + aoff + koff;
  const float* B = (Bsel >= 0 ? sel_ptr(Bsel) : Bext) + koff;
  float* C = sel_ptr(Csel) + coff;
  int tid = threadIdx.x;
  int tx = tid & 15, ty = tid >> 4;
  int tile = blockIdx.x;
  int m0 = (tile % nMt)*64, n0 = (tile / nMt)*64;
  int lr = tid >> 3;            // 0..31
  int ca = (tid & 7)*4;
  int rn0 = n0 + lr, rn1 = rn0 + 32;
  float4 ra0, ra1, rb0, rb1;
  const float4 z4 = make_float4(0.f,0.f,0.f,0.f);

  #define LDG_CHUNK(k0)                                                        \
    ra0 = *(const float4*)&A[(m0+lr)*lda + (k0) + ca];                         \
    ra1 = *(const float4*)&A[(m0+lr+32)*lda + (k0) + ca];                      \
    rb0 = (rn0 < Ncols) ? *(const float4*)&B[rn0*ldb + (k0) + ca] : z4;        \
    rb1 = (rn1 < Ncols) ? *(const float4*)&B[rn1*ldb + (k0) + ca] : z4;

  #define STS_CHUNK(buf)                                                       \
    As[buf][ca+0][lr] = ra0.x; As[buf][ca+1][lr] = ra0.y;                      \
    As[buf][ca+2][lr] = ra0.z; As[buf][ca+3][lr] = ra0.w;                      \
    As[buf][ca+0][lr+32] = ra1.x; As[buf][ca+1][lr+32] = ra1.y;                \
    As[buf][ca+2][lr+32] = ra1.z; As[buf][ca+3][lr+32] = ra1.w;                \
    Bs[buf][ca+0][lr] = rb0.x; Bs[buf][ca+1][lr] = rb0.y;                      \
    Bs[buf][ca+2][lr] = rb0.z; Bs[buf][ca+3][lr] = rb0.w;                      \
    Bs[buf][ca+0][lr+32] = rb1.x; Bs[buf][ca+1][lr+32] = rb1.y;                \
    Bs[buf][ca+2][lr+32] = rb1.z; Bs[buf][ca+3][lr+32] = rb1.w;

  float acc[4][4] = {};
  int nc = K/32;
  LDG_CHUNK(0); STS_CHUNK(0);
  __syncthreads();
  for (int c = 0; c < nc; c++) {
    if (c+1 < nc) { LDG_CHUNK((c+1)*32); }
    int buf = c & 1;
    #pragma unroll
    for (int k = 0; k < 32; k++) {
      float4 a4 = *(const float4*)&As[buf][k][ty*4];
      float4 b4 = *(const float4*)&Bs[buf][k][tx*4];
      acc[0][0] += a4.x*b4.x; acc[0][1] += a4.x*b4.y; acc[0][2] += a4.x*b4.z; acc[0][3] += a4.x*b4.w;
      acc[1][0] += a4.y*b4.x; acc[1][1] += a4.y*b4.y; acc[1][2] += a4.y*b4.z; acc[1][3] += a4.y*b4.w;
      acc[2][0] += a4.z*b4.x; acc[2][1] += a4.z*b4.y; acc[2][2] += a4.z*b4.z; acc[2][3] += a4.z*b4.w;
      acc[3][0] += a4.w*b4.x; acc[3][1] += a4.w*b4.y; acc[3][2] += a4.w*b4.z; acc[3][3] += a4.w*b4.w;
    }
    if (c+1 < nc) { STS_CHUNK((c+1)&1); }
    __syncthreads();
  }
  #pragma unroll
  for (int i = 0; i < 4; i++) {
    int mm = m0 + ty*4 + i;
    #pragma unroll
    for (int j = 0; j < 4; j++) {
      int nn = n0 + tx*4 + j;
      if (nn < Ncols) {
        float v = acc[i][j];
        if (ATOMIC) {
          atomicAdd(&C[mm*ldc + nn], v);
        } else {
          if (bias) v += bias[nn];
          if (ACT) v = fmaxf(v, 0.f);
          C[mm*ldc + nn] = v;
        }
      }
    }
  }
  #undef LDG_CHUNK
  #undef STS_CHUNK
}

// ---------------- CSR scatter with combined payload ----------------
__global__ void k_scatter(const int* __restrict__ esrc, const int* __restrict__ edst,
                          const float* __restrict__ eattr) {
  int e = blockIdx.x*256 + threadIdx.x;
  int p = atomicAdd(&g_cur[edst[e]], 1);
  g_edge[p] = make_float2(__int_as_float(esrc[e]), eattr[e]);
}

// ---------------- warp-per-node edge attention + aggregation -----------------
// One warp owns one node: no smem, no barriers, no cross-warp reduction.
// After the xor-shfl butterfly every lane holds the full dot product, so ev
// (and thus den) is lane-replicated for free.
__global__ void __launch_bounds__(256)
k_aggr(int w1off, const float* __restrict__ attl) {
  int n = (blockIdx.x*256 + threadIdx.x) >> 5;   // global warp id = node
  int lane = threadIdx.x & 31;
  int begin = g_off[n], cnt = g_off[n+1] - begin;
  const float4* xw4 = (const float4*)g_xWr;
  float4 wv = ((const float4*)(g_w1e + w1off))[lane];
  float4 av = ((const float4*)attl)[lane];
  float xr = g_xWr[n*136 + 128];
  float ax=0.f, ay=0.f, az=0.f, aw=0.f, den=0.f;
  for (int j0 = 0; j0 < cnt; j0 += 4) {
    int nv = cnt - j0; if (nv > 4) nv = 4;
    float2 ee[4]; float4 xx[4];
    float hx[4], hy[4], hz[4], hw[4], pp[4];
    #pragma unroll
    for (int u = 0; u < 4; u++) if (u < nv) ee[u] = g_edge[begin + j0 + u];   // broadcast
    #pragma unroll
    for (int u = 0; u < 4; u++) if (u < nv) xx[u] = xw4[__float_as_int(ee[u].x)*34 + lane];
    #pragma unroll
    for (int u = 0; u < 4; u++) {
      if (u < nv) {
        float ea = ee[u].y;
        hx[u] = lrelu(xx[u].x + ea*wv.x);
        hy[u] = lrelu(xx[u].y + ea*wv.y);
        hz[u] = lrelu(xx[u].z + ea*wv.z);
        hw[u] = lrelu(xx[u].w + ea*wv.w);
        pp[u] = hx[u]*av.x + hy[u]*av.y + hz[u]*av.z + hw[u]*av.w;
      } else pp[u] = 0.f;
    }
    #pragma unroll
    for (int s = 16; s > 0; s >>= 1) {
      #pragma unroll
      for (int u = 0; u < 4; u++) pp[u] += __shfl_xor_sync(0xffffffffu, pp[u], s);
    }
    #pragma unroll
    for (int u = 0; u < 4; u++) if (u < nv) {
      float ev = __expf(lrelu(pp[u] + xr));
      ax += ev*hx[u]; ay += ev*hy[u]; az += ev*hz[u]; aw += ev*hw[u];
      den += ev;
    }
  }
  float inv = 1.f/(den + 1e-16f);
  ((float4*)g_S)[n*32 + lane] = make_float4(ax*inv, ay*inv, az*inv, aw*inv);
}

// ---------------- fused pairwise MLP + masked row softmax (f32x2) ------------
__global__ void __launch_bounds__(256)
k_final(const float* __restrict__ b1, const float* __restrict__ W2,
        const float* __restrict__ b2, const float* __restrict__ m,
        float* __restrict__ out) {
  __shared__ unsigned long long ash2[8][10];       // packed (a+b1) col pairs
  __shared__ unsigned long long w2sh[10];
  __shared__ float rowM[8], rowInv[8];
  __shared__ __align__(16) float btile[256][22];   // stride 22 -> aligned b64; reused for reduce
  int tid = threadIdx.x;
  int i0 = blockIdx.x * 8;
  if (tid < 80) {
    int r = tid/10, cp = tid - r*10;
    float a0 = g_ab[(i0+r)*40 + 2*cp]   + b1[2*cp];
    float a1 = g_ab[(i0+r)*40 + 2*cp+1] + b1[2*cp+1];
    asm("mov.b64 %0, {%1, %2};" : "=l"(ash2[r][cp]) : "f"(a0), "f"(a1));
  }
  if (tid < 10) {
    asm("mov.b64 %0, {%1, %2};" : "=l"(w2sh[tid]) : "f"(W2[2*tid]), "f"(W2[2*tid+1]));
  }
  float b2v = b2[0];
  float omax[8], osum[8];
  #pragma unroll
  for (int r = 0; r < 8; r++) { omax[r] = -1e30f; osum[r] = 0.f; }
  __syncthreads();
  unsigned long long wr[10];
  #pragma unroll
  for (int cp = 0; cp < 10; cp++) wr[cp] = w2sh[cp];

  for (int jt = 0; jt < Nn; jt += 256) {
    __syncthreads();
    #pragma unroll
    for (int u = 0; u < 20; u++) {
      int l = u*256 + tid;
      int t = l / 20, c = l - t*20;
      btile[t][c] = g_ab[(jt+t)*40 + 20 + c];
    }
    __syncthreads();
    unsigned long long bl2[10];
    #pragma unroll
    for (int cp = 0; cp < 10; cp++)
      bl2[cp] = *(const unsigned long long*)&btile[tid][2*cp];
    int j = jt + tid;
    #pragma unroll
    for (int r = 0; r < 8; r++) {
      unsigned long long acc2 = 0ULL;      // (0.f, 0.f)
      #pragma unroll
      for (int cp = 0; cp < 10; cp++) {
        unsigned long long s;
        asm("add.rn.f32x2 %0, %1, %2;" : "=l"(s) : "l"(ash2[r][cp]), "l"(bl2[cp]));
        float lo, hi;
        asm("mov.b64 {%0, %1}, %2;" : "=f"(lo), "=f"(hi) : "l"(s));
        lo = fmaxf(lo, 0.f); hi = fmaxf(hi, 0.f);
        asm("mov.b64 %0, {%1, %2};" : "=l"(s) : "f"(lo), "f"(hi));
        asm("fma.rn.f32x2 %0, %1, %2, %3;" : "=l"(acc2) : "l"(s), "l"(wr[cp]), "l"(acc2));
      }
      float alo, ahi;
      asm("mov.b64 {%0, %1}, %2;" : "=f"(alo), "=f"(ahi) : "l"(acc2));
      size_t idx = (size_t)(i0+r)*Nn + j;
      float lv = (alo + ahi + b2v) * m[idx];
      out[idx] = lv;                       // park raw logit (L2-resident)
      float nm = fmaxf(omax[r], lv);
      osum[r] = osum[r]*__expf(omax[r]-nm) + __expf(lv-nm);
      omax[r] = nm;
    }
  }
  // (max,sum) merge: smem transpose + warp reduction (2 syncs)
  __syncthreads();
  float2* pr = (float2*)btile;
  #pragma unroll
  for (int r = 0; r < 8; r++) pr[r*256 + tid] = make_float2(omax[r], osum[r]);
  __syncthreads();
  int w = tid >> 5, lane = tid & 31;
  if (w < 8) {
    float M = -1e30f, S = 0.f;
    #pragma unroll
    for (int i = 0; i < 8; i++) {
      float2 v = pr[w*256 + lane + i*32];
      float nm = fmaxf(M, v.x);
      S = S*__expf(M-nm) + v.y*__expf(v.x-nm);
      M = nm;
    }
    #pragma unroll
    for (int s = 16; s > 0; s >>= 1) {
      float oM = __shfl_xor_sync(0xffffffffu, M, s);
      float oS = __shfl_xor_sync(0xffffffffu, S, s);
      float nm = fmaxf(M, oM);
      S = S*__expf(M-nm) + oS*__expf(oM-nm);
      M = nm;
    }
    if (lane == 0) { rowM[w] = M; rowInv[w] = 1.f/S; }
  }
  __syncthreads();
  for (int jt = 0; jt < Nn; jt += 256) {
    int j = jt + tid;
    #pragma unroll
    for (int r = 0; r < 8; r++) {
      size_t idx = (size_t)(i0+r)*Nn + j;
      out[idx] = __expf(out[idx] - rowM[r]) * rowInv[r];
    }
  }
}

// ---------------- driver ----------------
extern "C" void kernel_launch(void* const* d_in, const int* in_sizes, int n_in,
                              void* d_out, int out_size) {
  const int*   node_ids = (const int*)  d_in[0];
  const int*   eidx     = (const int*)  d_in[1];
  const float* eattr    = (const float*)d_in[2];
  const float* m        = (const float*)d_in[3];
  const float* emb      = (const float*)d_in[4];
  const float* l0_lin1  = (const float*)d_in[5];
  const float* l0_lin2  = (const float*)d_in[6];
  const float* l0_attl  = (const float*)d_in[7];
  const float* l0_attr  = (const float*)d_in[8];
  const float* l0_bias  = (const float*)d_in[9];
  const float* l1_lin1  = (const float*)d_in[10];
  const float* l1_lin2  = (const float*)d_in[11];
  const float* l1_attl  = (const float*)d_in[12];
  const float* l1_attr  = (const float*)d_in[13];
  const float* l1_bias  = (const float*)d_in[14];
  const float* W1       = (const float*)d_in[15];
  const float* b1       = (const float*)d_in[16];
  const float* W2       = (const float*)d_in[17];
  const float* b2       = (const float*)d_in[18];
  float* out = (float*)d_out;
  const int* esrc = eidx;
  const int* edst = eidx + Ee;

  k_setup<<<1237, 256>>>(node_ids, emb, W1, l0_lin1, l1_lin1, l0_attr, l1_attr, edst);

  // xW0 (96 tiles) + CSR scan (block 96)
  k_gemm<0,0><<<97, 256>>>(0, 0, 320, 4, nullptr, 64, nullptr, 2, 0, 136,
                           129, 64, 32, 96, 1);
  k_scatter<<<Ee/256, 256>>>(esrc, edst, eattr);
  k_aggr<<<Nn/8, 256>>>(0, l0_attl);
  k_gemm<1,0><<<64, 256>>>(1, 0, 128, -1, l0_lin2, 128, l0_bias, 0, 64, 320,
                           128, 128, 32, 64, 0);          // h1 -> feat cols 64..191
  k_gemm<0,0><<<96, 256>>>(0, 64, 320, 5, nullptr, 128, nullptr, 2, 0, 136,
                           129, 128, 32, 96, 0);          // xW1
  k_aggr<<<Nn/8, 256>>>(128, l1_attl);
  k_gemm<1,0><<<64, 256>>>(1, 0, 128, -1, l1_lin2, 128, l1_bias, 0, 192, 320,
                           128, 128, 32, 64, 0);          // h2 -> feat cols 192..319
  // ab split-K: grid (32 Mtiles, 5 K-chunks), atomicAdd into zeroed g_ab
  k_gemm<0,1><<<dim3(32, 5), 256>>>(0, 0, 320, 3, nullptr, 320, nullptr, 6, 0, 40,
                                    40, 64, 32, 32, 0);
  k_final<<<Nn/8, 256>>>(b1, W2, b2, m, out);
}

// round 9
// speedup vs baseline: 2.7398x; 1.0600x over previous
#include <cuda_runtime.h>

#define Nn 2048
#define Ee 65536

// ---------------- scratch (device globals; no allocations) ----------------
__device__ __align__(16) float g_feat[Nn*320];     // [x | h1 | h2]
__device__ __align__(16) float g_xWr[Nn*136];      // cols 0..127 = xW, col 128 = xr
__device__ __align__(16) float g_S[Nn*128];
__device__ __align__(16) float g_ab[Nn*40];        // zeroed in setup (split-K atomics)
__device__ __align__(16) float g_W1p[40*320];
__device__ __align__(16) float g_B0p[129*64];
__device__ __align__(16) float g_B1p[129*128];
__device__ __align__(16) float g_w1e[256];
__device__ __align__(16) float2 g_edge[Ee];        // CSR payload: (src bits, edge_attr)
__device__ int g_deg[Nn];                          // invariant: zero (restored by scan)
__device__ int g_off[Nn+1];
__device__ int g_cur[Nn];

__device__ __forceinline__ float lrelu(float x) { return x > 0.f ? x : 0.01f*x; }

__device__ __forceinline__ float* sel_ptr(int s) {
  switch (s) {
    case 0: return g_feat;
    case 1: return g_S;
    case 2: return g_xWr;
    case 3: return g_W1p;
    case 4: return g_B0p;
    case 5: return g_B1p;
    case 6: return g_ab;
    default: return nullptr;
  }
}

// ---------------- fused setup: embed + packs + hist + ab-zero ----------------
__global__ void k_setup(const int* __restrict__ ids, const float* __restrict__ emb,
                        const float* __restrict__ W1,
                        const float* __restrict__ l0_lin1, const float* __restrict__ l1_lin1,
                        const float* __restrict__ l0_attr, const float* __restrict__ l1_attr,
                        const int* __restrict__ edst) {
  int b = blockIdx.x, tid = threadIdx.x;
  if (b < 512) {
    int node = b*4 + (tid >> 6);
    int col = tid & 63;
    g_feat[node*320 + col] = emb[ids[node]*64 + col];
  } else if (b < 562) {
    int i = (b-512)*256 + tid;
    if (i < 40*320) {
      int r = i/320, c = i - r*320;
      g_W1p[i] = (r < 20) ? W1[r*640 + c] : W1[(r-20)*640 + 320 + c];
    }
  } else if (b == 562) {
    if (tid < 128) {
      g_w1e[tid]       = l0_lin1[tid*65  + 64];
      g_w1e[128 + tid] = l1_lin1[tid*129 + 128];
    }
  } else if (b < 596) {
    int i = (b-563)*256 + tid;
    if (i < 129*64) {
      int r = i >> 6, c = i & 63;
      g_B0p[i] = (r < 128) ? l0_lin1[r*65 + c] : l0_attr[c];
    }
  } else if (b < 661) {
    int i = (b-596)*256 + tid;
    if (i < 129*128) {
      int r = i >> 7, c = i & 127;
      g_B1p[i] = (r < 128) ? l1_lin1[r*129 + c] : l1_attr[c];
    }
  } else if (b < 917) {
    int e = (b-661)*256 + tid;
    atomicAdd(&g_deg[edst[e]], 1);
  } else {
    g_ab[(b-917)*256 + tid] = 0.f;     // 320 blocks: 81920 floats
  }
}

// ---------------- scan (256 threads), restores g_deg=0 ----------------
__device__ void dev_scan() {
  __shared__ int sw[8];
  int tid = threadIdx.x;
  int base = tid*8;
  int v[8], run = 0;
  #pragma unroll
  for (int i = 0; i < 8; i++) { v[i] = g_deg[base+i]; run += v[i]; }
  int lane = tid & 31, wid = tid >> 5;
  int incl = run;
  #pragma unroll
  for (int o = 1; o < 32; o <<= 1) {
    int u = __shfl_up_sync(0xffffffffu, incl, o);
    if (lane >= o) incl += u;
  }
  if (lane == 31) sw[wid] = incl;
  __syncthreads();
  if (tid == 0) {
    int acc = 0;
    #pragma unroll
    for (int w = 0; w < 8; w++) { int x = sw[w]; sw[w] = acc; acc += x; }
  }
  __syncthreads();
  int off = sw[wid] + incl - run;
  #pragma unroll
  for (int i = 0; i < 8; i++) {
    g_off[base+i] = off; g_cur[base+i] = off;
    off += v[i];
    g_deg[base+i] = 0;
  }
  if (tid == 0) g_off[2048] = Ee;
}

// ---------------- double-buffered 64x64 GEMM: C = act(A @ B^T + bias) --------
template<int ACT, int ATOMIC>
__global__ void __launch_bounds__(256)
k_gemm(int Asel, int aoff, int lda, int Bsel, const float* __restrict__ Bext, int ldb,
       const float* __restrict__ bias, int Csel, int coff, int ldc,
       int Ncols, int K, int nMt, int ntiles, int withScan) {
  if (withScan && (int)blockIdx.x == ntiles) { dev_scan(); return; }
  if ((int)blockIdx.x >= ntiles) return;
  __shared__ __align__(16) float As[2][32][68];
  __shared__ __align__(16) float Bs[2][32][68];
  int koff = blockIdx.y * 64;
  const float* A = sel_ptr(Asel) + aoff + koff;
  const float* B = (Bsel >= 0 ? sel_ptr(Bsel) : Bext) + koff;
  float* C = sel_ptr(Csel) + coff;
  int tid = threadIdx.x;
  int tx = tid & 15, ty = tid >> 4;
  int tile = blockIdx.x;
  int m0 = (tile % nMt)*64, n0 = (tile / nMt)*64;
  int lr = tid >> 3;            // 0..31
  int ca = (tid & 7)*4;
  int rn0 = n0 + lr, rn1 = rn0 + 32;
  float4 ra0, ra1, rb0, rb1;
  const float4 z4 = make_float4(0.f,0.f,0.f,0.f);

  #define LDG_CHUNK(k0)                                                        \
    ra0 = *(const float4*)&A[(m0+lr)*lda + (k0) + ca];                         \
    ra1 = *(const float4*)&A[(m0+lr+32)*lda + (k0) + ca];                      \
    rb0 = (rn0 < Ncols) ? *(const float4*)&B[rn0*ldb + (k0) + ca] : z4;        \
    rb1 = (rn1 < Ncols) ? *(const float4*)&B[rn1*ldb + (k0) + ca] : z4;

  #define STS_CHUNK(buf)                                                       \
    As[buf][ca+0][lr] = ra0.x; As[buf][ca+1][lr] = ra0.y;                      \
    As[buf][ca+2][lr] = ra0.z; As[buf][ca+3][lr] = ra0.w;                      \
    As[buf][ca+0][lr+32] = ra1.x; As[buf][ca+1][lr+32] = ra1.y;                \
    As[buf][ca+2][lr+32] = ra1.z; As[buf][ca+3][lr+32] = ra1.w;                \
    Bs[buf][ca+0][lr] = rb0.x; Bs[buf][ca+1][lr] = rb0.y;                      \
    Bs[buf][ca+2][lr] = rb0.z; Bs[buf][ca+3][lr] = rb0.w;                      \
    Bs[buf][ca+0][lr+32] = rb1.x; Bs[buf][ca+1][lr+32] = rb1.y;                \
    Bs[buf][ca+2][lr+32] = rb1.z; Bs[buf][ca+3][lr+32] = rb1.w;

  float acc[4][4] = {};
  int nc = K/32;
  LDG_CHUNK(0); STS_CHUNK(0);
  __syncthreads();
  for (int c = 0; c < nc; c++) {
    if (c+1 < nc) { LDG_CHUNK((c+1)*32); }
    int buf = c & 1;
    #pragma unroll
    for (int k = 0; k < 32; k++) {
      float4 a4 = *(const float4*)&As[buf][k][ty*4];
      float4 b4 = *(const float4*)&Bs[buf][k][tx*4];
      acc[0][0] += a4.x*b4.x; acc[0][1] += a4.x*b4.y; acc[0][2] += a4.x*b4.z; acc[0][3] += a4.x*b4.w;
      acc[1][0] += a4.y*b4.x; acc[1][1] += a4.y*b4.y; acc[1][2] += a4.y*b4.z; acc[1][3] += a4.y*b4.w;
      acc[2][0] += a4.z*b4.x; acc[2][1] += a4.z*b4.y; acc[2][2] += a4.z*b4.z; acc[2][3] += a4.z*b4.w;
      acc[3][0] += a4.w*b4.x; acc[3][1] += a4.w*b4.y; acc[3][2] += a4.w*b4.z; acc[3][3] += a4.w*b4.w;
    }
    if (c+1 < nc) { STS_CHUNK((c+1)&1); }
    __syncthreads();
  }
  #pragma unroll
  for (int i = 0; i < 4; i++) {
    int mm = m0 + ty*4 + i;
    #pragma unroll
    for (int j = 0; j < 4; j++) {
      int nn = n0 + tx*4 + j;
      if (nn < Ncols) {
        float v = acc[i][j];
        if (ATOMIC) {
          atomicAdd(&C[mm*ldc + nn], v);
        } else {
          if (bias) v += bias[nn];
          if (ACT) v = fmaxf(v, 0.f);
          C[mm*ldc + nn] = v;
        }
      }
    }
  }
  #undef LDG_CHUNK
  #undef STS_CHUNK
}

// ---------------- CSR scatter with combined payload ----------------
__global__ void k_scatter(const int* __restrict__ esrc, const int* __restrict__ edst,
                          const float* __restrict__ eattr) {
  int e = blockIdx.x*256 + threadIdx.x;
  int p = atomicAdd(&g_cur[edst[e]], 1);
  g_edge[p] = make_float2(__int_as_float(esrc[e]), eattr[e]);
}

// ---------------- 4-warps-per-node edge attention + aggregation --------------
// Block = 8 warps = 2 nodes. Each of a node's 4 warps handles a strided
// quarter of its edge list with 4-way ILP; one barrier combines the 4
// (numerator, denominator) partials. 1024 blocks -> 8192 warps resident.
__global__ void __launch_bounds__(256)
k_aggr(int w1off, const float* __restrict__ attl) {
  int tid = threadIdx.x;
  int w = tid >> 5, lane = tid & 31;
  int half = w >> 2;                 // 0 or 1: which node of this block
  int wi   = w & 3;                  // warp index within the node group
  int n = blockIdx.x*2 + half;
  int begin = g_off[n], cnt = g_off[n+1] - begin;
  const float4* xw4 = (const float4*)g_xWr;
  float4 wv = ((const float4*)(g_w1e + w1off))[lane];
  float4 av = ((const float4*)attl)[lane];
  float xr = g_xWr[n*136 + 128];
  float ax=0.f, ay=0.f, az=0.f, aw=0.f, den=0.f;
  for (int j0 = wi*4; j0 < cnt; j0 += 16) {
    int nv = cnt - j0; if (nv > 4) nv = 4;
    float2 ee[4]; float4 xx[4];
    float hx[4], hy[4], hz[4], hw[4], pp[4];
    #pragma unroll
    for (int u = 0; u < 4; u++) if (u < nv) ee[u] = g_edge[begin + j0 + u];   // broadcast
    #pragma unroll
    for (int u = 0; u < 4; u++) if (u < nv) xx[u] = xw4[__float_as_int(ee[u].x)*34 + lane];
    #pragma unroll
    for (int u = 0; u < 4; u++) {
      if (u < nv) {
        float ea = ee[u].y;
        hx[u] = lrelu(xx[u].x + ea*wv.x);
        hy[u] = lrelu(xx[u].y + ea*wv.y);
        hz[u] = lrelu(xx[u].z + ea*wv.z);
        hw[u] = lrelu(xx[u].w + ea*wv.w);
        pp[u] = hx[u]*av.x + hy[u]*av.y + hz[u]*av.z + hw[u]*av.w;
      } else pp[u] = 0.f;
    }
    #pragma unroll
    for (int s = 16; s > 0; s >>= 1) {
      #pragma unroll
      for (int u = 0; u < 4; u++) pp[u] += __shfl_xor_sync(0xffffffffu, pp[u], s);
    }
    #pragma unroll
    for (int u = 0; u < 4; u++) if (u < nv) {
      float ev = __expf(lrelu(pp[u] + xr));
      ax += ev*hx[u]; ay += ev*hy[u]; az += ev*hz[u]; aw += ev*hw[u];
      den += ev;
    }
  }
  __shared__ float4 red4[8][32];
  __shared__ float dred[8];
  red4[w][lane] = make_float4(ax, ay, az, aw);
  if (lane == 0) dred[w] = den;
  __syncthreads();
  if (wi == 0) {                     // warps 0 and 4 finalize their node
    float4 r = red4[w][lane];
    float d = dred[w];
    #pragma unroll
    for (int s = 1; s < 4; s++) {
      float4 o = red4[w+s][lane];
      r.x += o.x; r.y += o.y; r.z += o.z; r.w += o.w;
      d += dred[w+s];
    }
    float inv = 1.f/(d + 1e-16f);
    ((float4*)g_S)[n*32 + lane] = make_float4(r.x*inv, r.y*inv, r.z*inv, r.w*inv);
  }
}

// ---------------- fused pairwise MLP + masked row softmax (f32x2) ------------
__global__ void __launch_bounds__(256)
k_final(const float* __restrict__ b1, const float* __restrict__ W2,
        const float* __restrict__ b2, const float* __restrict__ m,
        float* __restrict__ out) {
  __shared__ unsigned long long ash2[8][10];       // packed (a+b1) col pairs
  __shared__ unsigned long long w2sh[10];
  __shared__ float rowM[8], rowInv[8];
  __shared__ __align__(16) float btile[256][22];   // stride 22 -> aligned b64; reused for reduce
  int tid = threadIdx.x;
  int i0 = blockIdx.x * 8;
  if (tid < 80) {
    int r = tid/10, cp = tid - r*10;
    float a0 = g_ab[(i0+r)*40 + 2*cp]   + b1[2*cp];
    float a1 = g_ab[(i0+r)*40 + 2*cp+1] + b1[2*cp+1];
    asm("mov.b64 %0, {%1, %2};" : "=l"(ash2[r][cp]) : "f"(a0), "f"(a1));
  }
  if (tid < 10) {
    asm("mov.b64 %0, {%1, %2};" : "=l"(w2sh[tid]) : "f"(W2[2*tid]), "f"(W2[2*tid+1]));
  }
  float b2v = b2[0];
  float omax[8], osum[8];
  #pragma unroll
  for (int r = 0; r < 8; r++) { omax[r] = -1e30f; osum[r] = 0.f; }
  __syncthreads();
  unsigned long long wr[10];
  #pragma unroll
  for (int cp = 0; cp < 10; cp++) wr[cp] = w2sh[cp];

  for (int jt = 0; jt < Nn; jt += 256) {
    __syncthreads();
    #pragma unroll
    for (int u = 0; u < 20; u++) {
      int l = u*256 + tid;
      int t = l / 20, c = l - t*20;
      btile[t][c] = g_ab[(jt+t)*40 + 20 + c];
    }
    __syncthreads();
    unsigned long long bl2[10];
    #pragma unroll
    for (int cp = 0; cp < 10; cp++)
      bl2[cp] = *(const unsigned long long*)&btile[tid][2*cp];
    int j = jt + tid;
    #pragma unroll
    for (int r = 0; r < 8; r++) {
      unsigned long long acc2 = 0ULL;      // (0.f, 0.f)
      #pragma unroll
      for (int cp = 0; cp < 10; cp++) {
        unsigned long long s;
        asm("add.rn.f32x2 %0, %1, %2;" : "=l"(s) : "l"(ash2[r][cp]), "l"(bl2[cp]));
        float lo, hi;
        asm("mov.b64 {%0, %1}, %2;" : "=f"(lo), "=f"(hi) : "l"(s));
        lo = fmaxf(lo, 0.f); hi = fmaxf(hi, 0.f);
        asm("mov.b64 %0, {%1, %2};" : "=l"(s) : "f"(lo), "f"(hi));
        asm("fma.rn.f32x2 %0, %1, %2, %3;" : "=l"(acc2) : "l"(s), "l"(wr[cp]), "l"(acc2));
      }
      float alo, ahi;
      asm("mov.b64 {%0, %1}, %2;" : "=f"(alo), "=f"(ahi) : "l"(acc2));
      size_t idx = (size_t)(i0+r)*Nn + j;
      float lv = (alo + ahi + b2v) * m[idx];
      out[idx] = lv;                       // park raw logit (L2-resident)
      float nm = fmaxf(omax[r], lv);
      osum[r] = osum[r]*__expf(omax[r]-nm) + __expf(lv-nm);
      omax[r] = nm;
    }
  }
  // (max,sum) merge: smem transpose + warp reduction (2 syncs)
  __syncthreads();
  float2* pr = (float2*)btile;
  #pragma unroll
  for (int r = 0; r < 8; r++) pr[r*256 + tid] = make_float2(omax[r], osum[r]);
  __syncthreads();
  int w = tid >> 5, lane = tid & 31;
  if (w < 8) {
    float M = -1e30f, S = 0.f;
    #pragma unroll
    for (int i = 0; i < 8; i++) {
      float2 v = pr[w*256 + lane + i*32];
      float nm = fmaxf(M, v.x);
      S = S*__expf(M-nm) + v.y*__expf(v.x-nm);
      M = nm;
    }
    #pragma unroll
    for (int s = 16; s > 0; s >>= 1) {
      float oM = __shfl_xor_sync(0xffffffffu, M, s);
      float oS = __shfl_xor_sync(0xffffffffu, S, s);
      float nm = fmaxf(M, oM);
      S = S*__expf(M-nm) + oS*__expf(oM-nm);
      M = nm;
    }
    if (lane == 0) { rowM[w] = M; rowInv[w] = 1.f/S; }
  }
  __syncthreads();
  for (int jt = 0; jt < Nn; jt += 256) {
    int j = jt + tid;
    #pragma unroll
    for (int r = 0; r < 8; r++) {
      size_t idx = (size_t)(i0+r)*Nn + j;
      out[idx] = __expf(out[idx] - rowM[r]) * rowInv[r];
    }
  }
}

// ---------------- driver ----------------
extern "C" void kernel_launch(void* const* d_in, const int* in_sizes, int n_in,
                              void* d_out, int out_size) {
  const int*   node_ids = (const int*)  d_in[0];
  const int*   eidx     = (const int*)  d_in[1];
  const float* eattr    = (const float*)d_in[2];
  const float* m        = (const float*)d_in[3];
  const float* emb      = (const float*)d_in[4];
  const float* l0_lin1  = (const float*)d_in[5];
  const float* l0_lin2  = (const float*)d_in[6];
  const float* l0_attl  = (const float*)d_in[7];
  const float* l0_attr  = (const float*)d_in[8];
  const float* l0_bias  = (const float*)d_in[9];
  const float* l1_lin1  = (const float*)d_in[10];
  const float* l1_lin2  = (const float*)d_in[11];
  const float* l1_attl  = (const float*)d_in[12];
  const float* l1_attr  = (const float*)d_in[13];
  const float* l1_bias  = (const float*)d_in[14];
  const float* W1       = (const float*)d_in[15];
  const float* b1       = (const float*)d_in[16];
  const float* W2       = (const float*)d_in[17];
  const float* b2       = (const float*)d_in[18];
  float* out = (float*)d_out;
  const int* esrc = eidx;
  const int* edst = eidx + Ee;

  k_setup<<<1237, 256>>>(node_ids, emb, W1, l0_lin1, l1_lin1, l0_attr, l1_attr, edst);

  // xW0 (96 tiles) + CSR scan (block 96)
  k_gemm<0,0><<<97, 256>>>(0, 0, 320, 4, nullptr, 64, nullptr, 2, 0, 136,
                           129, 64, 32, 96, 1);
  k_scatter<<<Ee/256, 256>>>(esrc, edst, eattr);
  k_aggr<<<Nn/2, 256>>>(0, l0_attl);
  k_gemm<1,0><<<64, 256>>>(1, 0, 128, -1, l0_lin2, 128, l0_bias, 0, 64, 320,
                           128, 128, 32, 64, 0);          // h1 -> feat cols 64..191
  k_gemm<0,0><<<96, 256>>>(0, 64, 320, 5, nullptr, 128, nullptr, 2, 0, 136,
                           129, 128, 32, 96, 0);          // xW1
  k_aggr<<<Nn/2, 256>>>(128, l1_attl);
  k_gemm<1,0><<<64, 256>>>(1, 0, 128, -1, l1_lin2, 128, l1_bias, 0, 192, 320,
                           128, 128, 32, 64, 0);          // h2 -> feat cols 192..319
  // ab split-K: grid (32 Mtiles, 5 K-chunks), atomicAdd into zeroed g_ab
  k_gemm<0,1><<<dim3(32, 5), 256>>>(0, 0, 320, 3, nullptr, 320, nullptr, 6, 0, 40,
                                    40, 64, 32, 32, 0);
  k_final<<<Nn/8, 256>>>(b1, W2, b2, m, out);
}